// round 1
// baseline (speedup 1.0000x reference)
#include <cuda_runtime.h>
#include <cuda_bf16.h>

// ---------------------------------------------------------------------------
// LGA attention, fp32 baseline.
// x:[256,196,768]; Wq/Wk/Wv/Wp:[768,768]; bp:[768]; conv_w:[768,1,3,3]; conv_b:[768]
// M = 256*196 = 50176, K = N = 768.
// ---------------------------------------------------------------------------

#define M_ROWS 50176
#define DIM 768
#define QKV_LD 2304

// Scratch (allocation-free rule: __device__ globals)
__device__ float g_qkv[(size_t)M_ROWS * QKV_LD];   // [row, {q|k|v} * 768]
__device__ float g_att[(size_t)M_ROWS * DIM];      // attention out + conv signature

// ---------------------------------------------------------------------------
// SGEMM: C[row, ccol0 + col] = A[row,:K] @ B[:,col] (+ bias[col0-rel])
// 128x128 tile, BK=16, 256 threads, 8x8 per thread.
// ---------------------------------------------------------------------------
template <bool BIAS>
__global__ __launch_bounds__(256) void sgemm_kernel(
    const float* __restrict__ A, const float* __restrict__ B,
    float* __restrict__ C, const float* __restrict__ bias,
    int K, int lda, int ldb, int ldc, int ccol0)
{
    __shared__ float As[16][132];   // [k][m], +4 pad
    __shared__ float Bs[16][128];   // [k][n]

    const int tid  = threadIdx.x;
    const int brow = blockIdx.x * 128;
    const int bcol = blockIdx.y * 128;
    const int tx = tid & 15;        // n-tile 0..15
    const int ty = tid >> 4;        // m-tile 0..15

    const float* Aptr = A + (size_t)brow * lda;
    const float* Bptr = B + bcol;

    float acc[8][8];
    #pragma unroll
    for (int i = 0; i < 8; ++i)
        #pragma unroll
        for (int j = 0; j < 8; ++j) acc[i][j] = 0.f;

    for (int k0 = 0; k0 < K; k0 += 16) {
        #pragma unroll
        for (int it = 0; it < 2; ++it) {
            int id  = tid + it * 256;           // 0..511
            int ar  = id >> 2, ac4 = id & 3;    // A: 128 rows x 4 float4
            float4 av = *(const float4*)(Aptr + (size_t)ar * lda + k0 + ac4 * 4);
            As[ac4 * 4 + 0][ar] = av.x;
            As[ac4 * 4 + 1][ar] = av.y;
            As[ac4 * 4 + 2][ar] = av.z;
            As[ac4 * 4 + 3][ar] = av.w;
            int br  = id >> 5, bc4 = id & 31;   // B: 16 rows x 32 float4
            float4 bv = *(const float4*)(Bptr + (size_t)(k0 + br) * ldb + bc4 * 4);
            *(float4*)(&Bs[br][bc4 * 4]) = bv;
        }
        __syncthreads();

        #pragma unroll
        for (int kk = 0; kk < 16; ++kk) {
            float a[8], b[8];
            *(float4*)(a)     = *(const float4*)(&As[kk][ty * 8]);
            *(float4*)(a + 4) = *(const float4*)(&As[kk][ty * 8 + 4]);
            *(float4*)(b)     = *(const float4*)(&Bs[kk][tx * 8]);
            *(float4*)(b + 4) = *(const float4*)(&Bs[kk][tx * 8 + 4]);
            #pragma unroll
            for (int i = 0; i < 8; ++i)
                #pragma unroll
                for (int j = 0; j < 8; ++j)
                    acc[i][j] += a[i] * b[j];
        }
        __syncthreads();
    }

    float bb[8];
    #pragma unroll
    for (int j = 0; j < 8; ++j)
        bb[j] = BIAS ? bias[bcol + tx * 8 + j] : 0.f;

    #pragma unroll
    for (int i = 0; i < 8; ++i) {
        size_t row = (size_t)(brow + ty * 8 + i);
        float* Crow = C + row * ldc + ccol0 + bcol + tx * 8;
        #pragma unroll
        for (int j4 = 0; j4 < 2; ++j4) {
            float4 v;
            v.x = acc[i][j4 * 4 + 0] + bb[j4 * 4 + 0];
            v.y = acc[i][j4 * 4 + 1] + bb[j4 * 4 + 1];
            v.z = acc[i][j4 * 4 + 2] + bb[j4 * 4 + 2];
            v.w = acc[i][j4 * 4 + 3] + bb[j4 * 4 + 3];
            *(float4*)(Crow + j4 * 4) = v;
        }
    }
}

// ---------------------------------------------------------------------------
// Grouped attention. One CTA per (group g in 49, head h in 12, bs in 32).
// seq = 32 (t1*t2*view = 2*2*8), d = 64. 128 threads.
// j -> token: view=j&7, t2=(j>>3)&1, t1=j>>4; r=t1*7+s1, c=t2*7+s2;
//             n=r*14+c, b=bs*8+view.
// ---------------------------------------------------------------------------
__global__ __launch_bounds__(128) void attn_kernel(
    const float* __restrict__ qkv, float* __restrict__ out)
{
    const int g  = blockIdx.x;   // 0..48
    const int h  = blockIdx.y;   // 0..11
    const int bs = blockIdx.z;   // 0..31
    const int s1 = g / 7, s2 = g % 7;
    const int tid = threadIdx.x;

    __shared__ float qs[32 * 65];
    __shared__ float ks2[32 * 65];
    __shared__ float vs[32 * 68];
    __shared__ float ps[32 * 33];
    __shared__ int   rowbase[32];

    if (tid < 32) {
        int j = tid;
        int view = j & 7, t2 = (j >> 3) & 1, t1 = j >> 4;
        int r = t1 * 7 + s1, c = t2 * 7 + s2;
        rowbase[j] = (bs * 8 + view) * 196 + r * 14 + c;
    }
    __syncthreads();

    #pragma unroll
    for (int it = 0; it < 4; ++it) {
        int id4 = tid + it * 128;         // 0..511  (32 rows x 16 float4)
        int row = id4 >> 4, d4 = id4 & 15;
        size_t base = (size_t)rowbase[row] * QKV_LD + h * 64 + d4 * 4;
        float4 qv = *(const float4*)(qkv + base);
        float4 kv = *(const float4*)(qkv + base + 768);
        float4 vv = *(const float4*)(qkv + base + 1536);
        int qo = row * 65 + d4 * 4;
        qs[qo] = qv.x; qs[qo + 1] = qv.y; qs[qo + 2] = qv.z; qs[qo + 3] = qv.w;
        ks2[qo] = kv.x; ks2[qo + 1] = kv.y; ks2[qo + 2] = kv.z; ks2[qo + 3] = kv.w;
        *(float4*)(vs + row * 68 + d4 * 4) = vv;
    }
    __syncthreads();

    const int i    = tid >> 2;   // query row 0..31
    const int quad = tid & 3;    // 8 keys each

    float s[8];
    #pragma unroll
    for (int jj = 0; jj < 8; ++jj) {
        int j = quad * 8 + jj;
        float acc = 0.f;
        #pragma unroll
        for (int k = 0; k < 64; ++k)
            acc += qs[i * 65 + k] * ks2[j * 65 + k];
        s[jj] = acc * 0.125f;    // 64^-0.5
    }
    float m = s[0];
    #pragma unroll
    for (int jj = 1; jj < 8; ++jj) m = fmaxf(m, s[jj]);
    m = fmaxf(m, __shfl_xor_sync(0xffffffffu, m, 1));
    m = fmaxf(m, __shfl_xor_sync(0xffffffffu, m, 2));
    float sum = 0.f;
    #pragma unroll
    for (int jj = 0; jj < 8; ++jj) { s[jj] = expf(s[jj] - m); sum += s[jj]; }
    sum += __shfl_xor_sync(0xffffffffu, sum, 1);
    sum += __shfl_xor_sync(0xffffffffu, sum, 2);
    float inv = 1.f / sum;
    #pragma unroll
    for (int jj = 0; jj < 8; ++jj)
        ps[i * 33 + quad * 8 + jj] = s[jj] * inv;
    __syncthreads();

    float o[16];
    #pragma unroll
    for (int dd = 0; dd < 16; ++dd) o[dd] = 0.f;
    #pragma unroll
    for (int j = 0; j < 32; ++j) {
        float p = ps[i * 33 + j];
        #pragma unroll
        for (int dd = 0; dd < 16; ++dd)
            o[dd] += p * vs[j * 68 + quad * 16 + dd];
    }
    size_t obase = (size_t)rowbase[i] * DIM + h * 64 + quad * 16;
    #pragma unroll
    for (int d4 = 0; d4 < 4; ++d4)
        *(float4*)(out + obase + d4 * 4) =
            make_float4(o[d4 * 4], o[d4 * 4 + 1], o[d4 * 4 + 2], o[d4 * 4 + 3]);
}

// ---------------------------------------------------------------------------
// Depthwise 3x3 SAME conv on v (channel = h*64+d), added into g_att.
// One CTA per (32-channel chunk, batch). Shared tile [196][32] pad 33.
// ---------------------------------------------------------------------------
__global__ __launch_bounds__(256) void conv_kernel(
    const float* __restrict__ qkv, const float* __restrict__ cw,
    const float* __restrict__ cb, float* __restrict__ out)
{
    const int chunk = blockIdx.x;   // 0..23
    const int b     = blockIdx.y;   // 0..255
    const int ch0   = chunk * 32;
    const int tid   = threadIdx.x;

    __shared__ float sh[196 * 33];

    for (int idx = tid; idx < 196 * 32; idx += 256) {
        int n = idx >> 5, cc = idx & 31;
        sh[n * 33 + cc] = qkv[(size_t)(b * 196 + n) * QKV_LD + 1536 + ch0 + cc];
    }
    __syncthreads();

    for (int idx = tid; idx < 196 * 32; idx += 256) {
        int n = idx >> 5, cc = idx & 31;
        int r = n / 14, c = n % 14;
        int ch = ch0 + cc;
        float acc = cb[ch];
        #pragma unroll
        for (int dr = -1; dr <= 1; ++dr) {
            int rr = r + dr;
            if (rr < 0 || rr > 13) continue;
            #pragma unroll
            for (int dc = -1; dc <= 1; ++dc) {
                int c2 = c + dc;
                if (c2 < 0 || c2 > 13) continue;
                acc += cw[ch * 9 + (dr + 1) * 3 + (dc + 1)]
                     * sh[(rr * 14 + c2) * 33 + cc];
            }
        }
        out[(size_t)(b * 196 + n) * DIM + ch] += acc;
    }
}

// ---------------------------------------------------------------------------
extern "C" void kernel_launch(void* const* d_in, const int* in_sizes, int n_in,
                              void* d_out, int out_size)
{
    const float* x  = (const float*)d_in[0];
    // d_in[1] = view_num (int32, == 8)
    const float* Wq = (const float*)d_in[2];
    const float* Wk = (const float*)d_in[3];
    const float* Wv = (const float*)d_in[4];
    const float* Wp = (const float*)d_in[5];
    const float* bp = (const float*)d_in[6];
    const float* cw = (const float*)d_in[7];
    const float* cb = (const float*)d_in[8];
    float* out = (float*)d_out;

    float *qkv_p = nullptr, *att_p = nullptr;
    cudaGetSymbolAddress((void**)&qkv_p, g_qkv);
    cudaGetSymbolAddress((void**)&att_p, g_att);

    dim3 gemm_grid(M_ROWS / 128, DIM / 128);   // (392, 6)

    // QKV projections -> g_qkv [row, 2304]
    sgemm_kernel<false><<<gemm_grid, 256>>>(x, Wq, qkv_p, nullptr, DIM, DIM, DIM, QKV_LD, 0);
    sgemm_kernel<false><<<gemm_grid, 256>>>(x, Wk, qkv_p, nullptr, DIM, DIM, DIM, QKV_LD, 768);
    sgemm_kernel<false><<<gemm_grid, 256>>>(x, Wv, qkv_p, nullptr, DIM, DIM, DIM, QKV_LD, 1536);

    // Grouped attention -> g_att [row, 768]
    attn_kernel<<<dim3(49, 12, 32), 128>>>(qkv_p, att_p);

    // Depthwise conv signature added into g_att
    conv_kernel<<<dim3(24, 256), 256>>>(qkv_p, cw, cb, att_p);

    // Output projection + bias -> d_out
    sgemm_kernel<true><<<gemm_grid, 256>>>(att_p, Wp, out, bp, DIM, DIM, DIM, DIM, 0);
}

// round 4
// speedup vs baseline: 2.2447x; 2.2447x over previous
#include <cuda_runtime.h>
#include <cuda_bf16.h>
#include <cstdint>

// ---------------------------------------------------------------------------
// LGA attention. GEMMs via mma.sync bf16 split (hi+lo) on the tensor pipe.
// x:[256,196,768]; Wq/Wk/Wv/Wp:[768,768]; bp:[768]; conv_w:[768,1,3,3]; conv_b:[768]
// M = 50176, K = 768, N(QKV fused) = 2304, N(proj) = 768.
// ---------------------------------------------------------------------------

#define M_ROWS 50176
#define DIM 768
#define QKV_LD 2304

__device__ float g_qkv[(size_t)M_ROWS * QKV_LD];
__device__ float g_att[(size_t)M_ROWS * DIM];
// Split-bf16 transposed weights: rows 0..2303 = [Wq|Wk|Wv] cols, 2304..3071 = Wp cols.
__device__ __nv_bfloat16 g_wt_hi[(size_t)3072 * DIM];
__device__ __nv_bfloat16 g_wt_lo[(size_t)3072 * DIM];

__device__ __forceinline__ void mma_bf16(float* d, const uint32_t* a, const uint32_t* b) {
    asm volatile(
        "mma.sync.aligned.m16n8k16.row.col.f32.bf16.bf16.f32 "
        "{%0,%1,%2,%3}, {%4,%5,%6,%7}, {%8,%9}, {%0,%1,%2,%3};\n"
        : "+f"(d[0]), "+f"(d[1]), "+f"(d[2]), "+f"(d[3])
        : "r"(a[0]), "r"(a[1]), "r"(a[2]), "r"(a[3]), "r"(b[0]), "r"(b[1]));
}

__device__ __forceinline__ void split2(float x, float y, uint32_t& hi, uint32_t& lo) {
    __nv_bfloat16 hx = __float2bfloat16(x);
    __nv_bfloat16 hy = __float2bfloat16(y);
    __nv_bfloat16 lx = __float2bfloat16(x - __bfloat162float(hx));
    __nv_bfloat16 ly = __float2bfloat16(y - __bfloat162float(hy));
    hi = (uint32_t)__bfloat16_as_ushort(hx) | ((uint32_t)__bfloat16_as_ushort(hy) << 16);
    lo = (uint32_t)__bfloat16_as_ushort(lx) | ((uint32_t)__bfloat16_as_ushort(ly) << 16);
}

// ---------------------------------------------------------------------------
// Weight prep: split + transpose into g_wt_hi/lo (rows = output cols).
// ---------------------------------------------------------------------------
__global__ __launch_bounds__(256) void wprep_kernel(
    const float* __restrict__ Wq, const float* __restrict__ Wk,
    const float* __restrict__ Wv, const float* __restrict__ Wp)
{
    int idx = blockIdx.x * 256 + threadIdx.x;
    if (idx >= 3072 * 768) return;
    int n = idx / 768, k = idx % 768;
    float w;
    if (n < 2304) {
        int sel = n / 768, col = n % 768;
        const float* W = (sel == 0) ? Wq : (sel == 1) ? Wk : Wv;
        w = W[k * 768 + col];
    } else {
        w = Wp[k * 768 + (n - 2304)];
    }
    __nv_bfloat16 h = __float2bfloat16(w);
    __nv_bfloat16 l = __float2bfloat16(w - __bfloat162float(h));
    g_wt_hi[(size_t)n * 768 + k] = h;
    g_wt_lo[(size_t)n * 768 + k] = l;
}

// ---------------------------------------------------------------------------
// HMMA split-bf16 GEMM: C[128,128 tile] = A_fp32[M,768] @ Bt^T (+bias)
// K-chunk 64. 256 threads = 8 warps (2 m x 4 n), warp tile 64x32.
// Smem rows: 64 bf16 data + 8 pad = 72 elem (144 B) -> conflict-free frag LDS.
// ---------------------------------------------------------------------------
#define TSTRIDE 72                       // elements per smem row
#define TILE_B  (128 * TSTRIDE * 2)      // 18432 bytes per tile
#define SM_AHI  0
#define SM_ALO  TILE_B
#define SM_BHI  (2 * TILE_B)
#define SM_BLO  (3 * TILE_B)
#define SM_TOTAL (4 * TILE_B)            // 73728

template <bool BIAS>
__global__ __launch_bounds__(256, 2) void hmma_gemm(
    const float* __restrict__ A,
    const __nv_bfloat16* __restrict__ Bhi,
    const __nv_bfloat16* __restrict__ Blo,
    float* __restrict__ C, const float* __restrict__ bias, int ldc)
{
    extern __shared__ char smem[];
    char* aHi = smem + SM_AHI;
    char* aLo = smem + SM_ALO;
    char* bHi = smem + SM_BHI;
    char* bLo = smem + SM_BLO;

    const int tid  = threadIdx.x;
    const int wid  = tid >> 5;
    const int lane = tid & 31;
    const int wm   = wid & 1;        // 0..1  (64-row slab)
    const int wn   = wid >> 1;       // 0..3  (32-col slab)
    const int g    = lane >> 2;      // 0..7
    const int tg   = lane & 3;       // 0..3
    const int brow = blockIdx.y * 128;
    const int bcol = blockIdx.x * 128;

    float acc[4][4][4];
    #pragma unroll
    for (int m = 0; m < 4; ++m)
        #pragma unroll
        for (int n = 0; n < 4; ++n)
            #pragma unroll
            for (int r = 0; r < 4; ++r) acc[m][n][r] = 0.f;

    for (int chunk = 0; chunk < 12; ++chunk) {
        const int k0 = chunk * 64;
        __syncthreads();

        // A: 128 rows x 16 float4 -> split hi/lo
        #pragma unroll
        for (int it = 0; it < 8; ++it) {
            int idx = tid + it * 256;        // 0..2047
            int row = idx >> 4, q = idx & 15;
            float4 v = *(const float4*)(A + (size_t)(brow + row) * 768 + k0 + q * 4);
            uint32_t h0, l0, h1, l1;
            split2(v.x, v.y, h0, l0);
            split2(v.z, v.w, h1, l1);
            uint32_t off = (uint32_t)(row * 144 + q * 8);
            *(uint2*)(aHi + off) = make_uint2(h0, h1);
            *(uint2*)(aLo + off) = make_uint2(l0, l1);
        }
        // B: hi & lo, 128 rows x 8 uint4 each
        #pragma unroll
        for (int it = 0; it < 8; ++it) {
            int idx = tid + it * 256;        // 0..2047
            int tile = idx >> 10, r = (idx >> 3) & 127, q = idx & 7;
            const __nv_bfloat16* src = (tile ? Blo : Bhi) + (size_t)(bcol + r) * 768 + k0 + q * 8;
            uint4 val = *(const uint4*)src;
            *(uint4*)((tile ? bLo : bHi) + (uint32_t)(r * 144 + q * 16)) = val;
        }
        __syncthreads();

        #pragma unroll
        for (int s = 0; s < 4; ++s) {
            const int kb = s * 16 + tg * 2;          // element offset in chunk
            uint32_t ah[4][4], al[4][4], bh[4][2], bl[4][2];
            #pragma unroll
            for (int m = 0; m < 4; ++m) {
                uint32_t ro = (uint32_t)((wm * 64 + m * 16 + g) * 144 + kb * 2);
                ah[m][0] = *(const uint32_t*)(aHi + ro);
                ah[m][1] = *(const uint32_t*)(aHi + ro + 8 * 144);
                ah[m][2] = *(const uint32_t*)(aHi + ro + 16);
                ah[m][3] = *(const uint32_t*)(aHi + ro + 8 * 144 + 16);
                al[m][0] = *(const uint32_t*)(aLo + ro);
                al[m][1] = *(const uint32_t*)(aLo + ro + 8 * 144);
                al[m][2] = *(const uint32_t*)(aLo + ro + 16);
                al[m][3] = *(const uint32_t*)(aLo + ro + 8 * 144 + 16);
            }
            #pragma unroll
            for (int n = 0; n < 4; ++n) {
                uint32_t ro = (uint32_t)((wn * 32 + n * 8 + g) * 144 + kb * 2);
                bh[n][0] = *(const uint32_t*)(bHi + ro);
                bh[n][1] = *(const uint32_t*)(bHi + ro + 16);
                bl[n][0] = *(const uint32_t*)(bLo + ro);
                bl[n][1] = *(const uint32_t*)(bLo + ro + 16);
            }
            #pragma unroll
            for (int m = 0; m < 4; ++m)
                #pragma unroll
                for (int n = 0; n < 4; ++n) {
                    mma_bf16(acc[m][n], ah[m], bh[n]);
                    mma_bf16(acc[m][n], ah[m], bl[n]);
                    mma_bf16(acc[m][n], al[m], bh[n]);
                }
        }
    }

    // Epilogue
    #pragma unroll
    for (int n = 0; n < 4; ++n) {
        int col = bcol + wn * 32 + n * 8 + tg * 2;
        float b0 = 0.f, b1 = 0.f;
        if (BIAS) { b0 = bias[col]; b1 = bias[col + 1]; }
        #pragma unroll
        for (int m = 0; m < 4; ++m) {
            int row0 = brow + wm * 64 + m * 16 + g;
            *(float2*)(C + (size_t)row0 * ldc + col) =
                make_float2(acc[m][n][0] + b0, acc[m][n][1] + b1);
            *(float2*)(C + (size_t)(row0 + 8) * ldc + col) =
                make_float2(acc[m][n][2] + b0, acc[m][n][3] + b1);
        }
    }
}

// ---------------------------------------------------------------------------
// Grouped attention (vectorized). One CTA per (group g, head h, bs).
// seq 32, d 64, 128 threads. Thread = (query i = tid>>2, quad = tid&3).
// ---------------------------------------------------------------------------
__global__ __launch_bounds__(128) void attn_kernel(
    const float* __restrict__ qkv, float* __restrict__ out)
{
    const int g  = blockIdx.x;   // 0..48
    const int h  = blockIdx.y;   // 0..11
    const int bs = blockIdx.z;   // 0..31
    const int s1 = g / 7, s2 = g % 7;
    const int tid = threadIdx.x;

    __shared__ float qs[32 * 68];
    __shared__ float ks2[32 * 68];
    __shared__ float vs[32 * 68];
    __shared__ float ps[32 * 33];
    __shared__ int   rowbase[32];

    if (tid < 32) {
        int j = tid;
        int view = j & 7, t2 = (j >> 3) & 1, t1 = j >> 4;
        int r = t1 * 7 + s1, c = t2 * 7 + s2;
        rowbase[j] = (bs * 8 + view) * 196 + r * 14 + c;
    }
    __syncthreads();

    #pragma unroll
    for (int it = 0; it < 4; ++it) {
        int id4 = tid + it * 128;
        int row = id4 >> 4, d4 = id4 & 15;
        size_t base = (size_t)rowbase[row] * QKV_LD + h * 64 + d4 * 4;
        *(float4*)(qs  + row * 68 + d4 * 4) = *(const float4*)(qkv + base);
        *(float4*)(ks2 + row * 68 + d4 * 4) = *(const float4*)(qkv + base + 768);
        *(float4*)(vs  + row * 68 + d4 * 4) = *(const float4*)(qkv + base + 1536);
    }
    __syncthreads();

    const int i    = tid >> 2;
    const int quad = tid & 3;

    float s[8];
    #pragma unroll
    for (int jj = 0; jj < 8; ++jj) s[jj] = 0.f;
    const float4* qp = (const float4*)(qs + i * 68);
    #pragma unroll
    for (int k4 = 0; k4 < 16; ++k4) {
        float4 a = qp[k4];
        #pragma unroll
        for (int jj = 0; jj < 8; ++jj) {
            float4 b = *(const float4*)(ks2 + (jj * 4 + quad) * 68 + k4 * 4);
            s[jj] += a.x * b.x + a.y * b.y + a.z * b.z + a.w * b.w;
        }
    }
    float m = s[0] * 0.125f;
    #pragma unroll
    for (int jj = 0; jj < 8; ++jj) { s[jj] *= 0.125f; m = fmaxf(m, s[jj]); }
    m = fmaxf(m, __shfl_xor_sync(0xffffffffu, m, 1));
    m = fmaxf(m, __shfl_xor_sync(0xffffffffu, m, 2));
    float sum = 0.f;
    #pragma unroll
    for (int jj = 0; jj < 8; ++jj) { s[jj] = expf(s[jj] - m); sum += s[jj]; }
    sum += __shfl_xor_sync(0xffffffffu, sum, 1);
    sum += __shfl_xor_sync(0xffffffffu, sum, 2);
    float inv = 1.f / sum;
    #pragma unroll
    for (int jj = 0; jj < 8; ++jj)
        ps[i * 33 + jj * 4 + quad] = s[jj] * inv;
    __syncthreads();

    float o[16];
    #pragma unroll
    for (int d = 0; d < 16; ++d) o[d] = 0.f;
    #pragma unroll
    for (int j = 0; j < 32; ++j) {
        float p = ps[i * 33 + j];
        const float* vrow = vs + j * 68 + quad * 4;
        #pragma unroll
        for (int u = 0; u < 4; ++u) {
            float4 vv = *(const float4*)(vrow + u * 16);
            o[u * 4 + 0] += p * vv.x;
            o[u * 4 + 1] += p * vv.y;
            o[u * 4 + 2] += p * vv.z;
            o[u * 4 + 3] += p * vv.w;
        }
    }
    size_t obase = (size_t)rowbase[i] * DIM + h * 64 + quad * 4;
    #pragma unroll
    for (int u = 0; u < 4; ++u)
        *(float4*)(out + obase + u * 16) =
            make_float4(o[u * 4], o[u * 4 + 1], o[u * 4 + 2], o[u * 4 + 3]);
}

// ---------------------------------------------------------------------------
// Depthwise 3x3 SAME conv on v, added into g_att.
// ---------------------------------------------------------------------------
__global__ __launch_bounds__(256) void conv_kernel(
    const float* __restrict__ qkv, const float* __restrict__ cw,
    const float* __restrict__ cb, float* __restrict__ out)
{
    const int chunk = blockIdx.x;   // 0..23
    const int b     = blockIdx.y;   // 0..255
    const int ch0   = chunk * 32;
    const int tid   = threadIdx.x;

    __shared__ float sh[196 * 33];

    for (int idx = tid; idx < 196 * 32; idx += 256) {
        int n = idx >> 5, cc = idx & 31;
        sh[n * 33 + cc] = qkv[(size_t)(b * 196 + n) * QKV_LD + 1536 + ch0 + cc];
    }
    __syncthreads();

    for (int idx = tid; idx < 196 * 32; idx += 256) {
        int n = idx >> 5, cc = idx & 31;
        int r = n / 14, c = n % 14;
        int ch = ch0 + cc;
        float acc = cb[ch];
        #pragma unroll
        for (int dr = -1; dr <= 1; ++dr) {
            int rr = r + dr;
            if (rr < 0 || rr > 13) continue;
            #pragma unroll
            for (int dc = -1; dc <= 1; ++dc) {
                int c2 = c + dc;
                if (c2 < 0 || c2 > 13) continue;
                acc += cw[ch * 9 + (dr + 1) * 3 + (dc + 1)]
                     * sh[(rr * 14 + c2) * 33 + cc];
            }
        }
        out[(size_t)(b * 196 + n) * DIM + ch] += acc;
    }
}

// ---------------------------------------------------------------------------
extern "C" void kernel_launch(void* const* d_in, const int* in_sizes, int n_in,
                              void* d_out, int out_size)
{
    const float* x  = (const float*)d_in[0];
    const float* Wq = (const float*)d_in[2];
    const float* Wk = (const float*)d_in[3];
    const float* Wv = (const float*)d_in[4];
    const float* Wp = (const float*)d_in[5];
    const float* bp = (const float*)d_in[6];
    const float* cw = (const float*)d_in[7];
    const float* cb = (const float*)d_in[8];
    float* out = (float*)d_out;

    float *qkv_p = nullptr, *att_p = nullptr;
    __nv_bfloat16 *wth = nullptr, *wtl = nullptr;
    cudaGetSymbolAddress((void**)&qkv_p, g_qkv);
    cudaGetSymbolAddress((void**)&att_p, g_att);
    cudaGetSymbolAddress((void**)&wth, g_wt_hi);
    cudaGetSymbolAddress((void**)&wtl, g_wt_lo);

    cudaFuncSetAttribute(hmma_gemm<false>, cudaFuncAttributeMaxDynamicSharedMemorySize, SM_TOTAL);
    cudaFuncSetAttribute(hmma_gemm<true>,  cudaFuncAttributeMaxDynamicSharedMemorySize, SM_TOTAL);

    // Weight split+transpose
    wprep_kernel<<<(3072 * 768 + 255) / 256, 256>>>(Wq, Wk, Wv, Wp);

    // QKV projections (fused N=2304) -> g_qkv
    hmma_gemm<false><<<dim3(18, 392), 256, SM_TOTAL>>>(x, wth, wtl, qkv_p, nullptr, QKV_LD);

    // Grouped attention -> g_att
    attn_kernel<<<dim3(49, 12, 32), 128>>>(qkv_p, att_p);

    // Depthwise conv signature added into g_att
    conv_kernel<<<dim3(24, 256), 256>>>(qkv_p, cw, cb, att_p);

    // Output projection + bias -> d_out
    hmma_gemm<true><<<dim3(6, 392), 256, SM_TOTAL>>>(
        att_p, wth + (size_t)2304 * 768, wtl + (size_t)2304 * 768, out, bp, DIM);
}

// round 7
// speedup vs baseline: 2.4033x; 1.0707x over previous
#include <cuda_runtime.h>
#include <cuda_bf16.h>
#include <cstdint>

// ---------------------------------------------------------------------------
// LGA attention. Split-bf16 (hi+lo, 3-pass) HMMA GEMMs, cp.async double-buffer.
// M = 50176, K = 768, N(QKV fused) = 2304, N(proj) = 768.
// ---------------------------------------------------------------------------

#define M_ROWS 50176
#define DIM 768
#define QKV_LD 2304

__device__ float g_qkv[(size_t)M_ROWS * QKV_LD];
__device__ float g_att[(size_t)M_ROWS * DIM];
__device__ __nv_bfloat16 g_x_hi[(size_t)M_ROWS * DIM];
__device__ __nv_bfloat16 g_x_lo[(size_t)M_ROWS * DIM];
__device__ __nv_bfloat16 g_att_hi[(size_t)M_ROWS * DIM];
__device__ __nv_bfloat16 g_att_lo[(size_t)M_ROWS * DIM];
// Split-bf16 transposed weights: rows 0..2303 = [Wq|Wk|Wv] cols, 2304..3071 = Wp cols.
__device__ __nv_bfloat16 g_wt_hi[(size_t)3072 * DIM];
__device__ __nv_bfloat16 g_wt_lo[(size_t)3072 * DIM];

__device__ __forceinline__ void mma_bf16(float* d, const uint32_t* a, const uint32_t* b) {
    asm volatile(
        "mma.sync.aligned.m16n8k16.row.col.f32.bf16.bf16.f32 "
        "{%0,%1,%2,%3}, {%4,%5,%6,%7}, {%8,%9}, {%0,%1,%2,%3};\n"
        : "+f"(d[0]), "+f"(d[1]), "+f"(d[2]), "+f"(d[3])
        : "r"(a[0]), "r"(a[1]), "r"(a[2]), "r"(a[3]), "r"(b[0]), "r"(b[1]));
}

__device__ __forceinline__ void split2(float x, float y, uint32_t& hi, uint32_t& lo) {
    __nv_bfloat16 hx = __float2bfloat16(x);
    __nv_bfloat16 hy = __float2bfloat16(y);
    __nv_bfloat16 lx = __float2bfloat16(x - __bfloat162float(hx));
    __nv_bfloat16 ly = __float2bfloat16(y - __bfloat162float(hy));
    hi = (uint32_t)__bfloat16_as_ushort(hx) | ((uint32_t)__bfloat16_as_ushort(hy) << 16);
    lo = (uint32_t)__bfloat16_as_ushort(lx) | ((uint32_t)__bfloat16_as_ushort(ly) << 16);
}

__device__ __forceinline__ uint32_t smem_u32(const void* p) {
    uint32_t a;
    asm("{ .reg .u64 t; cvta.to.shared.u64 t, %1; cvt.u32.u64 %0, t; }" : "=r"(a) : "l"(p));
    return a;
}
__device__ __forceinline__ void cp16(uint32_t dst, const void* src) {
    asm volatile("cp.async.cg.shared.global [%0], [%1], 16;" :: "r"(dst), "l"(src));
}

// ---------------------------------------------------------------------------
// Weight prep: split + transpose into g_wt_hi/lo (rows = output cols).
// ---------------------------------------------------------------------------
__global__ __launch_bounds__(256) void wprep_kernel(
    const float* __restrict__ Wq, const float* __restrict__ Wk,
    const float* __restrict__ Wv, const float* __restrict__ Wp)
{
    int idx = blockIdx.x * 256 + threadIdx.x;
    if (idx >= 3072 * 768) return;
    int n = idx / 768, k = idx % 768;
    float w;
    if (n < 2304) {
        int sel = n / 768, col = n % 768;
        const float* W = (sel == 0) ? Wq : (sel == 1) ? Wk : Wv;
        w = W[k * 768 + col];
    } else {
        w = Wp[k * 768 + (n - 2304)];
    }
    __nv_bfloat16 h = __float2bfloat16(w);
    __nv_bfloat16 l = __float2bfloat16(w - __bfloat162float(h));
    g_wt_hi[(size_t)n * 768 + k] = h;
    g_wt_lo[(size_t)n * 768 + k] = l;
}

// ---------------------------------------------------------------------------
// x prep: split x fp32 -> g_x_hi / g_x_lo bf16.
// ---------------------------------------------------------------------------
__global__ __launch_bounds__(256) void xprep_kernel(const float* __restrict__ x)
{
    size_t idx = ((size_t)blockIdx.x * 256 + threadIdx.x) * 4;
    if (idx >= (size_t)M_ROWS * DIM) return;
    float4 v = *(const float4*)(x + idx);
    uint32_t h0, l0, h1, l1;
    split2(v.x, v.y, h0, l0);
    split2(v.z, v.w, h1, l1);
    *(uint2*)(g_x_hi + idx) = make_uint2(h0, h1);
    *(uint2*)(g_x_lo + idx) = make_uint2(l0, l1);
}

// ---------------------------------------------------------------------------
// HMMA split-bf16 GEMM, cp.async double-buffered.
// Tile 256x128, K-chunk 64, 512 threads = 16 warps (4m x 4n), warp tile 64x32.
// Smem rows padded to 144 B. Stage = Ahi+Alo (256x144) + Bhi+Blo (128x144).
// ---------------------------------------------------------------------------
#define A_TILE_B  (256 * 144)            // 36864
#define B_TILE_B  (128 * 144)            // 18432
#define STAGE_B   (2 * A_TILE_B + 2 * B_TILE_B)   // 110592
#define GSM_TOTAL (2 * STAGE_B)          // 221184

template <bool BIAS>
__global__ __launch_bounds__(512, 1) void hmma_gemm(
    const __nv_bfloat16* __restrict__ Ahi, const __nv_bfloat16* __restrict__ Alo,
    const __nv_bfloat16* __restrict__ Bhi, const __nv_bfloat16* __restrict__ Blo,
    float* __restrict__ C, const float* __restrict__ bias, int ldc)
{
    extern __shared__ char smem[];
    const uint32_t sbase = smem_u32(smem);

    const int tid  = threadIdx.x;
    const int wid  = tid >> 5;
    const int lane = tid & 31;
    const int wm   = wid & 3;        // 0..3  (64-row slab of 256)
    const int wn   = wid >> 2;       // 0..3  (32-col slab of 128)
    const int g    = lane >> 2;      // 0..7
    const int tg   = lane & 3;       // 0..3
    const int brow = blockIdx.y * 256;
    const int bcol = blockIdx.x * 128;

    float acc[4][4][4];
    #pragma unroll
    for (int m = 0; m < 4; ++m)
        #pragma unroll
        for (int n = 0; n < 4; ++n)
            #pragma unroll
            for (int r = 0; r < 4; ++r) acc[m][n][r] = 0.f;

    // ---- loader ----
    auto load_stage = [&](int st, int chunk) {
        const int k0 = chunk * 64;
        const uint32_t sa = sbase + st * STAGE_B;
        #pragma unroll
        for (int it = 0; it < 4; ++it) {
            int idx = tid + it * 512;            // 0..2047
            int row = idx >> 3, q = idx & 7;
            size_t go = (size_t)(brow + row) * 768 + k0 + q * 8;
            uint32_t so = (uint32_t)(row * 144 + q * 16);
            cp16(sa + so,            Ahi + go);
            cp16(sa + A_TILE_B + so, Alo + go);
        }
        #pragma unroll
        for (int it = 0; it < 2; ++it) {
            int idx = tid + it * 512;            // 0..1023
            int row = idx >> 3, q = idx & 7;
            size_t go = (size_t)(bcol + row) * 768 + k0 + q * 8;
            uint32_t so = (uint32_t)(row * 144 + q * 16);
            cp16(sa + 2 * A_TILE_B + so,             Bhi + go);
            cp16(sa + 2 * A_TILE_B + B_TILE_B + so,  Blo + go);
        }
        asm volatile("cp.async.commit_group;");
    };

    load_stage(0, 0);

    for (int c = 0; c < 12; ++c) {
        if (c < 11) {
            load_stage((c + 1) & 1, c + 1);
            asm volatile("cp.async.wait_group 1;");
        } else {
            asm volatile("cp.async.wait_group 0;");
        }
        __syncthreads();

        const char* sa = smem + (c & 1) * STAGE_B;
        const char* aHi = sa;
        const char* aLo = sa + A_TILE_B;
        const char* bHi = sa + 2 * A_TILE_B;
        const char* bLo = sa + 2 * A_TILE_B + B_TILE_B;

        #pragma unroll
        for (int s = 0; s < 4; ++s) {
            const int kb = s * 16 + tg * 2;      // element offset in chunk
            uint32_t bh[4][2], bl[4][2];
            #pragma unroll
            for (int n = 0; n < 4; ++n) {
                uint32_t ro = (uint32_t)((wn * 32 + n * 8 + g) * 144 + kb * 2);
                bh[n][0] = *(const uint32_t*)(bHi + ro);
                bh[n][1] = *(const uint32_t*)(bHi + ro + 16);
                bl[n][0] = *(const uint32_t*)(bLo + ro);
                bl[n][1] = *(const uint32_t*)(bLo + ro + 16);
            }
            #pragma unroll
            for (int m = 0; m < 4; ++m) {
                uint32_t ro = (uint32_t)((wm * 64 + m * 16 + g) * 144 + kb * 2);
                uint32_t ah[4], al[4];
                ah[0] = *(const uint32_t*)(aHi + ro);
                ah[1] = *(const uint32_t*)(aHi + ro + 8 * 144);
                ah[2] = *(const uint32_t*)(aHi + ro + 16);
                ah[3] = *(const uint32_t*)(aHi + ro + 8 * 144 + 16);
                al[0] = *(const uint32_t*)(aLo + ro);
                al[1] = *(const uint32_t*)(aLo + ro + 8 * 144);
                al[2] = *(const uint32_t*)(aLo + ro + 16);
                al[3] = *(const uint32_t*)(aLo + ro + 8 * 144 + 16);
                #pragma unroll
                for (int n = 0; n < 4; ++n) {
                    mma_bf16(acc[m][n], ah, bh[n]);
                    mma_bf16(acc[m][n], ah, bl[n]);
                    mma_bf16(acc[m][n], al, bh[n]);
                }
            }
        }
        __syncthreads();
    }

    // Epilogue
    #pragma unroll
    for (int n = 0; n < 4; ++n) {
        int col = bcol + wn * 32 + n * 8 + tg * 2;
        float b0 = 0.f, b1 = 0.f;
        if (BIAS) { b0 = bias[col]; b1 = bias[col + 1]; }
        #pragma unroll
        for (int m = 0; m < 4; ++m) {
            int row0 = brow + wm * 64 + m * 16 + g;
            *(float2*)(C + (size_t)row0 * ldc + col) =
                make_float2(acc[m][n][0] + b0, acc[m][n][1] + b1);
            *(float2*)(C + (size_t)(row0 + 8) * ldc + col) =
                make_float2(acc[m][n][2] + b0, acc[m][n][3] + b1);
        }
    }
}

// ---------------------------------------------------------------------------
// Grouped attention (vectorized). One CTA per (group g, head h, bs).
// ---------------------------------------------------------------------------
__global__ __launch_bounds__(128) void attn_kernel(
    const float* __restrict__ qkv, float* __restrict__ out)
{
    const int g  = blockIdx.x;   // 0..48
    const int h  = blockIdx.y;   // 0..11
    const int bs = blockIdx.z;   // 0..31
    const int s1 = g / 7, s2 = g % 7;
    const int tid = threadIdx.x;

    __shared__ float qs[32 * 68];
    __shared__ float ks2[32 * 68];
    __shared__ float vs[32 * 68];
    __shared__ float ps[32 * 33];
    __shared__ int   rowbase[32];

    if (tid < 32) {
        int j = tid;
        int view = j & 7, t2 = (j >> 3) & 1, t1 = j >> 4;
        int r = t1 * 7 + s1, c = t2 * 7 + s2;
        rowbase[j] = (bs * 8 + view) * 196 + r * 14 + c;
    }
    __syncthreads();

    #pragma unroll
    for (int it = 0; it < 4; ++it) {
        int id4 = tid + it * 128;
        int row = id4 >> 4, d4 = id4 & 15;
        size_t base = (size_t)rowbase[row] * QKV_LD + h * 64 + d4 * 4;
        *(float4*)(qs  + row * 68 + d4 * 4) = *(const float4*)(qkv + base);
        *(float4*)(ks2 + row * 68 + d4 * 4) = *(const float4*)(qkv + base + 768);
        *(float4*)(vs  + row * 68 + d4 * 4) = *(const float4*)(qkv + base + 1536);
    }
    __syncthreads();

    const int i    = tid >> 2;
    const int quad = tid & 3;

    float s[8];
    #pragma unroll
    for (int jj = 0; jj < 8; ++jj) s[jj] = 0.f;
    const float4* qp = (const float4*)(qs + i * 68);
    #pragma unroll
    for (int k4 = 0; k4 < 16; ++k4) {
        float4 a = qp[k4];
        #pragma unroll
        for (int jj = 0; jj < 8; ++jj) {
            float4 b = *(const float4*)(ks2 + (jj * 4 + quad) * 68 + k4 * 4);
            s[jj] += a.x * b.x + a.y * b.y + a.z * b.z + a.w * b.w;
        }
    }
    float m = s[0] * 0.125f;
    #pragma unroll
    for (int jj = 0; jj < 8; ++jj) { s[jj] *= 0.125f; m = fmaxf(m, s[jj]); }
    m = fmaxf(m, __shfl_xor_sync(0xffffffffu, m, 1));
    m = fmaxf(m, __shfl_xor_sync(0xffffffffu, m, 2));
    float sum = 0.f;
    #pragma unroll
    for (int jj = 0; jj < 8; ++jj) { s[jj] = expf(s[jj] - m); sum += s[jj]; }
    sum += __shfl_xor_sync(0xffffffffu, sum, 1);
    sum += __shfl_xor_sync(0xffffffffu, sum, 2);
    float inv = 1.f / sum;
    #pragma unroll
    for (int jj = 0; jj < 8; ++jj)
        ps[i * 33 + jj * 4 + quad] = s[jj] * inv;
    __syncthreads();

    float o[16];
    #pragma unroll
    for (int d = 0; d < 16; ++d) o[d] = 0.f;
    #pragma unroll
    for (int j = 0; j < 32; ++j) {
        float p = ps[i * 33 + j];
        const float* vrow = vs + j * 68 + quad * 4;
        #pragma unroll
        for (int u = 0; u < 4; ++u) {
            float4 vv = *(const float4*)(vrow + u * 16);
            o[u * 4 + 0] += p * vv.x;
            o[u * 4 + 1] += p * vv.y;
            o[u * 4 + 2] += p * vv.z;
            o[u * 4 + 3] += p * vv.w;
        }
    }
    size_t obase = (size_t)rowbase[i] * DIM + h * 64 + quad * 4;
    #pragma unroll
    for (int u = 0; u < 4; ++u)
        *(float4*)(out + obase + u * 16) =
            make_float4(o[u * 4], o[u * 4 + 1], o[u * 4 + 2], o[u * 4 + 3]);
}

// ---------------------------------------------------------------------------
// Depthwise 3x3 conv (padded halo tile) + att add + split to hi/lo bf16.
// One CTA per (32-channel chunk, batch). No bounds branches in taps.
// ---------------------------------------------------------------------------
__global__ __launch_bounds__(256) void conv_split_kernel(
    const float* __restrict__ qkv, const float* __restrict__ att,
    const float* __restrict__ cw, const float* __restrict__ cb,
    __nv_bfloat16* __restrict__ ahi, __nv_bfloat16* __restrict__ alo)
{
    const int chunk = blockIdx.x;   // 0..23
    const int b     = blockIdx.y;   // 0..255
    const int ch0   = chunk * 32;
    const int tid   = threadIdx.x;

    __shared__ float sh[256 * 32];   // padded 16x16 grid x 32 ch
    __shared__ float w9[32 * 9];
    __shared__ float bb[32];

    // zero (incl. halo)
    #pragma unroll
    for (int i = tid; i < 2048; i += 256)
        ((float4*)sh)[i] = make_float4(0.f, 0.f, 0.f, 0.f);
    for (int i = tid; i < 32 * 9; i += 256)      // FIX: 288 > blockDim, stride loop
        w9[i] = cw[ch0 * 9 + i];
    if (tid < 32) bb[tid] = cb[ch0 + tid];
    __syncthreads();

    // interior load: 196 tokens x 8 float4
    for (int idx = tid; idx < 196 * 8; idx += 256) {
        int n = idx >> 3, q = idx & 7;
        int r = n / 14, c = n % 14;
        float4 v = *(const float4*)(qkv + (size_t)(b * 196 + n) * QKV_LD + 1536 + ch0 + q * 4);
        *(float4*)&sh[((r + 1) * 16 + (c + 1)) * 32 + q * 4] = v;
    }
    __syncthreads();

    // compute: 2 channels per thread
    for (int idx = tid; idx < 196 * 16; idx += 256) {
        int n = idx >> 4, cp = idx & 15;
        int r = n / 14, c = n % 14;
        int p0 = (r + 1) * 16 + (c + 1);
        int cc = cp * 2;
        float a0 = bb[cc], a1 = bb[cc + 1];
        #pragma unroll
        for (int dr = -1; dr <= 1; ++dr)
            #pragma unroll
            for (int dc = -1; dc <= 1; ++dc) {
                int t = (dr + 1) * 3 + (dc + 1);
                const float* sp = &sh[(p0 + dr * 16 + dc) * 32 + cc];
                a0 += w9[cc * 9 + t] * sp[0];
                a1 += w9[(cc + 1) * 9 + t] * sp[1];
            }
        size_t o = (size_t)(b * 196 + n) * DIM + ch0 + cc;
        a0 += att[o];
        a1 += att[o + 1];
        uint32_t h, l;
        split2(a0, a1, h, l);
        *(uint32_t*)(ahi + o) = h;
        *(uint32_t*)(alo + o) = l;
    }
}

// ---------------------------------------------------------------------------
extern "C" void kernel_launch(void* const* d_in, const int* in_sizes, int n_in,
                              void* d_out, int out_size)
{
    const float* x  = (const float*)d_in[0];
    const float* Wq = (const float*)d_in[2];
    const float* Wk = (const float*)d_in[3];
    const float* Wv = (const float*)d_in[4];
    const float* Wp = (const float*)d_in[5];
    const float* bp = (const float*)d_in[6];
    const float* cw = (const float*)d_in[7];
    const float* cb = (const float*)d_in[8];
    float* out = (float*)d_out;

    float *qkv_p = nullptr, *att_p = nullptr;
    __nv_bfloat16 *wth = nullptr, *wtl = nullptr;
    __nv_bfloat16 *xhi = nullptr, *xlo = nullptr, *athi = nullptr, *atlo = nullptr;
    cudaGetSymbolAddress((void**)&qkv_p, g_qkv);
    cudaGetSymbolAddress((void**)&att_p, g_att);
    cudaGetSymbolAddress((void**)&wth, g_wt_hi);
    cudaGetSymbolAddress((void**)&wtl, g_wt_lo);
    cudaGetSymbolAddress((void**)&xhi, g_x_hi);
    cudaGetSymbolAddress((void**)&xlo, g_x_lo);
    cudaGetSymbolAddress((void**)&athi, g_att_hi);
    cudaGetSymbolAddress((void**)&atlo, g_att_lo);

    cudaFuncSetAttribute(hmma_gemm<false>, cudaFuncAttributeMaxDynamicSharedMemorySize, GSM_TOTAL);
    cudaFuncSetAttribute(hmma_gemm<true>,  cudaFuncAttributeMaxDynamicSharedMemorySize, GSM_TOTAL);

    // Prep: weight split+transpose, x split
    wprep_kernel<<<(3072 * 768 + 255) / 256, 256>>>(Wq, Wk, Wv, Wp);
    xprep_kernel<<<(M_ROWS * DIM / 4 + 255) / 256, 256>>>(x);

    // QKV projections (fused N=2304) -> g_qkv
    hmma_gemm<false><<<dim3(18, 196), 512, GSM_TOTAL>>>(
        xhi, xlo, wth, wtl, qkv_p, nullptr, QKV_LD);

    // Grouped attention -> g_att (fp32)
    attn_kernel<<<dim3(49, 12, 32), 128>>>(qkv_p, att_p);

    // Conv + add + split -> g_att_hi/lo
    conv_split_kernel<<<dim3(24, 256), 256>>>(qkv_p, att_p, cw, cb, athi, atlo);

    // Output projection + bias -> d_out
    hmma_gemm<true><<<dim3(6, 196), 512, GSM_TOTAL>>>(
        athi, atlo, wth + (size_t)2304 * 768, wtl + (size_t)2304 * 768, out, bp, DIM);
}

// round 13
// speedup vs baseline: 2.9968x; 1.2469x over previous
#include <cuda_runtime.h>
#include <cuda_fp16.h>
#include <cstdint>

// ---------------------------------------------------------------------------
// LGA attention. fp16 2-pass GEMMs (A fp16, W split hi+lo fp16), cp.async x3.
// M = 50176, K = 768, N(QKV fused) = 2304, N(proj) = 768.
// ---------------------------------------------------------------------------

#define M_ROWS 50176
#define DIM 768
#define QKV_LD 2304

__device__ float g_qkv[(size_t)M_ROWS * QKV_LD];
__device__ float g_att[(size_t)M_ROWS * DIM];
__device__ __half g_x_h[(size_t)M_ROWS * DIM];
__device__ __half g_att_h[(size_t)M_ROWS * DIM];
// fp16 transposed weights: rows 0..2303 = [Wq|Wk|Wv] cols, 2304..3071 = Wp cols.
__device__ __half g_wt_hi[(size_t)3072 * DIM];
__device__ __half g_wt_lo[(size_t)3072 * DIM];

__device__ __forceinline__ void mma_f16(float* d, const uint32_t* a, const uint32_t* b) {
    asm volatile(
        "mma.sync.aligned.m16n8k16.row.col.f32.f16.f16.f32 "
        "{%0,%1,%2,%3}, {%4,%5,%6,%7}, {%8,%9}, {%0,%1,%2,%3};\n"
        : "+f"(d[0]), "+f"(d[1]), "+f"(d[2]), "+f"(d[3])
        : "r"(a[0]), "r"(a[1]), "r"(a[2]), "r"(a[3]), "r"(b[0]), "r"(b[1]));
}

__device__ __forceinline__ uint32_t smem_u32(const void* p) {
    uint32_t a;
    asm("{ .reg .u64 t; cvta.to.shared.u64 t, %1; cvt.u32.u64 %0, t; }" : "=r"(a) : "l"(p));
    return a;
}
__device__ __forceinline__ void cp16(uint32_t dst, const void* src) {
    asm volatile("cp.async.cg.shared.global [%0], [%1], 16;" :: "r"(dst), "l"(src));
}

// ---------------------------------------------------------------------------
// Weight prep: split + transpose into g_wt_hi/lo (rows = output cols).
// ---------------------------------------------------------------------------
__global__ __launch_bounds__(256) void wprep_kernel(
    const float* __restrict__ Wq, const float* __restrict__ Wk,
    const float* __restrict__ Wv, const float* __restrict__ Wp)
{
    int idx = blockIdx.x * 256 + threadIdx.x;
    if (idx >= 3072 * 768) return;
    int n = idx / 768, k = idx % 768;
    float w;
    if (n < 2304) {
        int sel = n / 768, col = n % 768;
        const float* W = (sel == 0) ? Wq : (sel == 1) ? Wk : Wv;
        w = W[k * 768 + col];
    } else {
        w = Wp[k * 768 + (n - 2304)];
    }
    __half h = __float2half_rn(w);
    __half l = __float2half_rn(w - __half2float(h));
    g_wt_hi[(size_t)n * 768 + k] = h;
    g_wt_lo[(size_t)n * 768 + k] = l;
}

// ---------------------------------------------------------------------------
// x prep: round x fp32 -> fp16.
// ---------------------------------------------------------------------------
__global__ __launch_bounds__(256) void xprep_kernel(const float* __restrict__ x)
{
    size_t idx = ((size_t)blockIdx.x * 256 + threadIdx.x) * 4;
    if (idx >= (size_t)M_ROWS * DIM) return;
    float4 v = *(const float4*)(x + idx);
    __half2 a = __floats2half2_rn(v.x, v.y);
    __half2 b = __floats2half2_rn(v.z, v.w);
    *(uint2*)(g_x_h + idx) = make_uint2(*(uint32_t*)&a, *(uint32_t*)&b);
}

// ---------------------------------------------------------------------------
// HMMA fp16 2-pass GEMM, cp.async 3-stage.
// Tile 256x128, K-chunk 64, 512 threads = 16 warps (4m x 4n), warp tile 64x32.
// Smem rows 128 B data + 16 pad = 144 B. Stage = A(256x144) + Bhi+Blo (128x144).
// ---------------------------------------------------------------------------
#define A_TILE_B  (256 * 144)                     // 36864
#define B_TILE_B  (128 * 144)                     // 18432
#define STAGE_B   (A_TILE_B + 2 * B_TILE_B)       // 73728
#define GSM_TOTAL (3 * STAGE_B)                   // 221184

template <bool BIAS>
__global__ __launch_bounds__(512, 1) void hmma_gemm(
    const __half* __restrict__ A,
    const __half* __restrict__ Bhi, const __half* __restrict__ Blo,
    float* __restrict__ C, const float* __restrict__ bias, int ldc)
{
    extern __shared__ char smem[];
    const uint32_t sbase = smem_u32(smem);

    const int tid  = threadIdx.x;
    const int wid  = tid >> 5;
    const int lane = tid & 31;
    const int wm   = wid & 3;        // 0..3  (64-row slab of 256)
    const int wn   = wid >> 2;       // 0..3  (32-col slab of 128)
    const int g    = lane >> 2;      // 0..7
    const int tg   = lane & 3;       // 0..3
    const int brow = blockIdx.y * 256;
    const int bcol = blockIdx.x * 128;

    float acc[4][4][4];
    #pragma unroll
    for (int m = 0; m < 4; ++m)
        #pragma unroll
        for (int n = 0; n < 4; ++n)
            #pragma unroll
            for (int r = 0; r < 4; ++r) acc[m][n][r] = 0.f;

    auto load_stage = [&](int st, int chunk) {
        const int k0 = chunk * 64;
        const uint32_t sa = sbase + st * STAGE_B;
        #pragma unroll
        for (int it = 0; it < 4; ++it) {            // A: 256 rows x 8 x 16B
            int idx = tid + it * 512;
            int row = idx >> 3, q = idx & 7;
            cp16(sa + (uint32_t)(row * 144 + q * 16),
                 A + (size_t)(brow + row) * 768 + k0 + q * 8);
        }
        #pragma unroll
        for (int it = 0; it < 4; ++it) {            // Bhi/Blo: 2 x 128 rows x 8
            int idx = tid + it * 512;
            int tile = idx >> 10, row = (idx >> 3) & 127, q = idx & 7;
            const __half* src = (tile ? Blo : Bhi) + (size_t)(bcol + row) * 768 + k0 + q * 8;
            cp16(sa + A_TILE_B + tile * B_TILE_B + (uint32_t)(row * 144 + q * 16), src);
        }
        asm volatile("cp.async.commit_group;");
    };

    load_stage(0, 0);
    load_stage(1, 1);

    for (int c = 0; c < 12; ++c) {
        if (c <= 9) {
            load_stage((c + 2) % 3, c + 2);
            asm volatile("cp.async.wait_group 2;");
        } else if (c == 10) {
            asm volatile("cp.async.wait_group 1;");
        } else {
            asm volatile("cp.async.wait_group 0;");
        }
        __syncthreads();

        const char* sa  = smem + (c % 3) * STAGE_B;
        const char* aP  = sa;
        const char* bHi = sa + A_TILE_B;
        const char* bLo = sa + A_TILE_B + B_TILE_B;

        #pragma unroll
        for (int s = 0; s < 4; ++s) {
            const int kb = s * 16 + tg * 2;      // element offset in chunk
            uint32_t bh[4][2], bl[4][2];
            #pragma unroll
            for (int n = 0; n < 4; ++n) {
                uint32_t ro = (uint32_t)((wn * 32 + n * 8 + g) * 144 + kb * 2);
                bh[n][0] = *(const uint32_t*)(bHi + ro);
                bh[n][1] = *(const uint32_t*)(bHi + ro + 16);
                bl[n][0] = *(const uint32_t*)(bLo + ro);
                bl[n][1] = *(const uint32_t*)(bLo + ro + 16);
            }
            #pragma unroll
            for (int m = 0; m < 4; ++m) {
                uint32_t ro = (uint32_t)((wm * 64 + m * 16 + g) * 144 + kb * 2);
                uint32_t a[4];
                a[0] = *(const uint32_t*)(aP + ro);
                a[1] = *(const uint32_t*)(aP + ro + 8 * 144);
                a[2] = *(const uint32_t*)(aP + ro + 16);
                a[3] = *(const uint32_t*)(aP + ro + 8 * 144 + 16);
                #pragma unroll
                for (int n = 0; n < 4; ++n) {
                    mma_f16(acc[m][n], a, bh[n]);
                    mma_f16(acc[m][n], a, bl[n]);
                }
            }
        }
        __syncthreads();
    }

    // Epilogue
    #pragma unroll
    for (int n = 0; n < 4; ++n) {
        int col = bcol + wn * 32 + n * 8 + tg * 2;
        float b0 = 0.f, b1 = 0.f;
        if (BIAS) { b0 = bias[col]; b1 = bias[col + 1]; }
        #pragma unroll
        for (int m = 0; m < 4; ++m) {
            int row0 = brow + wm * 64 + m * 16 + g;
            *(float2*)(C + (size_t)row0 * ldc + col) =
                make_float2(acc[m][n][0] + b0, acc[m][n][1] + b1);
            *(float2*)(C + (size_t)(row0 + 8) * ldc + col) =
                make_float2(acc[m][n][2] + b0, acc[m][n][3] + b1);
        }
    }
}

// ---------------------------------------------------------------------------
// Grouped attention, register-blocked, 2 heads per CTA.
// seq 32, d 64. 128 threads: hh = tid>>6 selects head, t = tid&63.
// QK: 4 queries x 4 keys per thread. PV: 4 queries x 8 dims per thread.
// PSS=34: PV read addrs (q4*4+qi)*34 land on banks {0,8,16,24} -> conflict-free.
// ---------------------------------------------------------------------------
#define PSS 34
#define ATTN_HEADF (3 * 2176 + 32 * PSS)        // qs+ks+vs+ps per head
#define ATTN_SMEM  ((2 * ATTN_HEADF) * 4 + 128) // + rowbase

__global__ __launch_bounds__(128) void attn_kernel(
    const float* __restrict__ qkv, float* __restrict__ out)
{
    extern __shared__ float sm[];
    const int g  = blockIdx.x;   // 0..48
    const int hp = blockIdx.y;   // 0..5 (head pair)
    const int bs = blockIdx.z;   // 0..31
    const int s1 = g / 7, s2 = g % 7;
    const int tid = threadIdx.x;
    const int hh = tid >> 6, t = tid & 63;
    const int h  = hp * 2 + hh;

    float* qs = sm + hh * ATTN_HEADF;
    float* ks = qs + 2176;
    float* vs = ks + 2176;
    float* ps = vs + 2176;
    int* rowbase = (int*)(sm + 2 * ATTN_HEADF);

    if (tid < 32) {
        int j = tid;
        int view = j & 7, t2 = (j >> 3) & 1, t1 = j >> 4;
        rowbase[j] = (bs * 8 + view) * 196 + (t1 * 7 + s1) * 14 + (t2 * 7 + s2);
    }
    __syncthreads();

    // load q/k/v for this head: 3 arrays x 512 float4, 64 threads
    #pragma unroll
    for (int it = 0; it < 24; ++it) {
        int idx = t + it * 64;            // 0..1535
        int arr = idx >> 9;               // 0..2
        int r = (idx >> 4) & 31, d4 = idx & 15;
        size_t base = (size_t)rowbase[r] * QKV_LD + h * 64 + d4 * 4 + arr * 768;
        float* dst = (arr == 0) ? qs : (arr == 1) ? ks : vs;
        *(float4*)(dst + r * 68 + d4 * 4) = *(const float4*)(qkv + base);
    }
    __syncthreads();

    // ---- QK: queries {is + 8qi}, keys {js + 8kj} ----
    {
        const int is = t >> 3, js = t & 7;
        float s[4][4];
        #pragma unroll
        for (int a = 0; a < 4; ++a)
            #pragma unroll
            for (int b = 0; b < 4; ++b) s[a][b] = 0.f;

        #pragma unroll
        for (int k4 = 0; k4 < 16; ++k4) {
            float4 qv[4], kv[4];
            #pragma unroll
            for (int qi = 0; qi < 4; ++qi)
                qv[qi] = *(const float4*)(qs + (is + 8 * qi) * 68 + k4 * 4);
            #pragma unroll
            for (int kj = 0; kj < 4; ++kj)
                kv[kj] = *(const float4*)(ks + (js + 8 * kj) * 68 + k4 * 4);
            #pragma unroll
            for (int qi = 0; qi < 4; ++qi)
                #pragma unroll
                for (int kj = 0; kj < 4; ++kj)
                    s[qi][kj] += qv[qi].x * kv[kj].x + qv[qi].y * kv[kj].y
                               + qv[qi].z * kv[kj].z + qv[qi].w * kv[kj].w;
        }
        #pragma unroll
        for (int qi = 0; qi < 4; ++qi) {
            float mm = s[qi][0] * 0.125f;
            #pragma unroll
            for (int kj = 0; kj < 4; ++kj) { s[qi][kj] *= 0.125f; mm = fmaxf(mm, s[qi][kj]); }
            mm = fmaxf(mm, __shfl_xor_sync(0xffffffffu, mm, 1));
            mm = fmaxf(mm, __shfl_xor_sync(0xffffffffu, mm, 2));
            mm = fmaxf(mm, __shfl_xor_sync(0xffffffffu, mm, 4));
            float sum = 0.f;
            #pragma unroll
            for (int kj = 0; kj < 4; ++kj) { s[qi][kj] = expf(s[qi][kj] - mm); sum += s[qi][kj]; }
            sum += __shfl_xor_sync(0xffffffffu, sum, 1);
            sum += __shfl_xor_sync(0xffffffffu, sum, 2);
            sum += __shfl_xor_sync(0xffffffffu, sum, 4);
            float inv = 1.f / sum;
            #pragma unroll
            for (int kj = 0; kj < 4; ++kj)
                ps[(is + 8 * qi) * PSS + js + 8 * kj] = s[qi][kj] * inv;
        }
    }
    __syncthreads();

    // ---- PV: queries {q4*4 + qi}, dims {ds*8 .. +7} ----
    {
        const int q4 = t >> 3, ds = t & 7;
        float o[4][8];
        #pragma unroll
        for (int a = 0; a < 4; ++a)
            #pragma unroll
            for (int b = 0; b < 8; ++b) o[a][b] = 0.f;

        #pragma unroll 4
        for (int j = 0; j < 32; ++j) {
            float4 v0 = *(const float4*)(vs + j * 68 + ds * 8);
            float4 v1 = *(const float4*)(vs + j * 68 + ds * 8 + 4);
            #pragma unroll
            for (int qi = 0; qi < 4; ++qi) {
                float p = ps[(q4 * 4 + qi) * PSS + j];
                o[qi][0] += p * v0.x; o[qi][1] += p * v0.y;
                o[qi][2] += p * v0.z; o[qi][3] += p * v0.w;
                o[qi][4] += p * v1.x; o[qi][5] += p * v1.y;
                o[qi][6] += p * v1.z; o[qi][7] += p * v1.w;
            }
        }
        #pragma unroll
        for (int qi = 0; qi < 4; ++qi) {
            size_t ob = (size_t)rowbase[q4 * 4 + qi] * DIM + h * 64 + ds * 8;
            *(float4*)(out + ob)     = make_float4(o[qi][0], o[qi][1], o[qi][2], o[qi][3]);
            *(float4*)(out + ob + 4) = make_float4(o[qi][4], o[qi][5], o[qi][6], o[qi][7]);
        }
    }
}

// ---------------------------------------------------------------------------
// Depthwise 3x3 conv (padded halo) + att add -> fp16 A for proj GEMM.
// ---------------------------------------------------------------------------
__global__ __launch_bounds__(256) void conv_split_kernel(
    const float* __restrict__ qkv, const float* __restrict__ att,
    const float* __restrict__ cw, const float* __restrict__ cb,
    __half* __restrict__ ah)
{
    const int chunk = blockIdx.x;   // 0..23
    const int b     = blockIdx.y;   // 0..255
    const int ch0   = chunk * 32;
    const int tid   = threadIdx.x;

    __shared__ float sh[256 * 32];   // padded 16x16 grid x 32 ch
    __shared__ float w9[32 * 9];
    __shared__ float bb[32];

    #pragma unroll
    for (int i = tid; i < 2048; i += 256)
        ((float4*)sh)[i] = make_float4(0.f, 0.f, 0.f, 0.f);
    for (int i = tid; i < 32 * 9; i += 256)
        w9[i] = cw[ch0 * 9 + i];
    if (tid < 32) bb[tid] = cb[ch0 + tid];
    __syncthreads();

    for (int idx = tid; idx < 196 * 8; idx += 256) {
        int n = idx >> 3, q = idx & 7;
        int r = n / 14, c = n % 14;
        float4 v = *(const float4*)(qkv + (size_t)(b * 196 + n) * QKV_LD + 1536 + ch0 + q * 4);
        *(float4*)&sh[((r + 1) * 16 + (c + 1)) * 32 + q * 4] = v;
    }
    __syncthreads();

    for (int idx = tid; idx < 196 * 16; idx += 256) {
        int n = idx >> 4, cp = idx & 15;
        int r = n / 14, c = n % 14;
        int p0 = (r + 1) * 16 + (c + 1);
        int cc = cp * 2;
        float a0 = bb[cc], a1 = bb[cc + 1];
        #pragma unroll
        for (int dr = -1; dr <= 1; ++dr)
            #pragma unroll
            for (int dc = -1; dc <= 1; ++dc) {
                int tp = (dr + 1) * 3 + (dc + 1);
                const float* sp = &sh[(p0 + dr * 16 + dc) * 32 + cc];
                a0 += w9[cc * 9 + tp] * sp[0];
                a1 += w9[(cc + 1) * 9 + tp] * sp[1];
            }
        size_t o = (size_t)(b * 196 + n) * DIM + ch0 + cc;
        a0 += att[o];
        a1 += att[o + 1];
        __half2 hv = __floats2half2_rn(a0, a1);
        *(uint32_t*)(ah + o) = *(uint32_t*)&hv;
    }
}

// ---------------------------------------------------------------------------
extern "C" void kernel_launch(void* const* d_in, const int* in_sizes, int n_in,
                              void* d_out, int out_size)
{
    const float* x  = (const float*)d_in[0];
    const float* Wq = (const float*)d_in[2];
    const float* Wk = (const float*)d_in[3];
    const float* Wv = (const float*)d_in[4];
    const float* Wp = (const float*)d_in[5];
    const float* bp = (const float*)d_in[6];
    const float* cw = (const float*)d_in[7];
    const float* cb = (const float*)d_in[8];
    float* out = (float*)d_out;

    float *qkv_p = nullptr, *att_p = nullptr;
    __half *wth = nullptr, *wtl = nullptr, *xh = nullptr, *ath = nullptr;
    cudaGetSymbolAddress((void**)&qkv_p, g_qkv);
    cudaGetSymbolAddress((void**)&att_p, g_att);
    cudaGetSymbolAddress((void**)&wth, g_wt_hi);
    cudaGetSymbolAddress((void**)&wtl, g_wt_lo);
    cudaGetSymbolAddress((void**)&xh, g_x_h);
    cudaGetSymbolAddress((void**)&ath, g_att_h);

    cudaFuncSetAttribute(hmma_gemm<false>, cudaFuncAttributeMaxDynamicSharedMemorySize, GSM_TOTAL);
    cudaFuncSetAttribute(hmma_gemm<true>,  cudaFuncAttributeMaxDynamicSharedMemorySize, GSM_TOTAL);
    cudaFuncSetAttribute(attn_kernel, cudaFuncAttributeMaxDynamicSharedMemorySize, ATTN_SMEM);

    // Prep: weight split+transpose, x round
    wprep_kernel<<<(3072 * 768 + 255) / 256, 256>>>(Wq, Wk, Wv, Wp);
    xprep_kernel<<<(M_ROWS * DIM / 4 + 255) / 256, 256>>>(x);

    // QKV projections (fused N=2304) -> g_qkv fp32
    hmma_gemm<false><<<dim3(18, 196), 512, GSM_TOTAL>>>(
        xh, wth, wtl, qkv_p, nullptr, QKV_LD);

    // Grouped attention -> g_att (fp32), 2 heads per CTA
    attn_kernel<<<dim3(49, 6, 32), 128, ATTN_SMEM>>>(qkv_p, att_p);

    // Conv + add -> fp16 A
    conv_split_kernel<<<dim3(24, 256), 256>>>(qkv_p, att_p, cw, cb, ath);

    // Output projection + bias -> d_out
    hmma_gemm<true><<<dim3(6, 196), 512, GSM_TOTAL>>>(
        ath, wth + (size_t)2304 * 768, wtl + (size_t)2304 * 768, out, bp, DIM);
}

// round 14
// speedup vs baseline: 3.2637x; 1.0891x over previous
#include <cuda_runtime.h>
#include <cuda_fp16.h>
#include <cstdint>

// ---------------------------------------------------------------------------
// LGA attention. fp16 2-pass GEMMs (A fp16, W split hi+lo fp16), cp.async x3.
// M = 50176, K = 768, N(QKV fused) = 2304, N(proj) = 768.
// ---------------------------------------------------------------------------

#define M_ROWS 50176
#define DIM 768
#define QKV_LD 2304

__device__ float g_qkv[(size_t)M_ROWS * QKV_LD];
__device__ float g_att[(size_t)M_ROWS * DIM];
__device__ __half g_x_h[(size_t)M_ROWS * DIM];
__device__ __half g_att_h[(size_t)M_ROWS * DIM];
// fp16 transposed weights: rows 0..2303 = [Wq|Wk|Wv] cols, 2304..3071 = Wp cols.
__device__ __half g_wt_hi[(size_t)3072 * DIM];
__device__ __half g_wt_lo[(size_t)3072 * DIM];

__device__ __forceinline__ void mma_f16(float* d, const uint32_t* a, const uint32_t* b) {
    asm volatile(
        "mma.sync.aligned.m16n8k16.row.col.f32.f16.f16.f32 "
        "{%0,%1,%2,%3}, {%4,%5,%6,%7}, {%8,%9}, {%0,%1,%2,%3};\n"
        : "+f"(d[0]), "+f"(d[1]), "+f"(d[2]), "+f"(d[3])
        : "r"(a[0]), "r"(a[1]), "r"(a[2]), "r"(a[3]), "r"(b[0]), "r"(b[1]));
}

__device__ __forceinline__ uint32_t smem_u32(const void* p) {
    uint32_t a;
    asm("{ .reg .u64 t; cvta.to.shared.u64 t, %1; cvt.u32.u64 %0, t; }" : "=r"(a) : "l"(p));
    return a;
}
__device__ __forceinline__ void cp16(uint32_t dst, const void* src) {
    asm volatile("cp.async.cg.shared.global [%0], [%1], 16;" :: "r"(dst), "l"(src));
}

// ---------------------------------------------------------------------------
// Weight prep: split + transpose into g_wt_hi/lo (rows = output cols).
// ---------------------------------------------------------------------------
__global__ __launch_bounds__(256) void wprep_kernel(
    const float* __restrict__ Wq, const float* __restrict__ Wk,
    const float* __restrict__ Wv, const float* __restrict__ Wp)
{
    int idx = blockIdx.x * 256 + threadIdx.x;
    if (idx >= 3072 * 768) return;
    int n = idx / 768, k = idx % 768;
    float w;
    if (n < 2304) {
        int sel = n / 768, col = n % 768;
        const float* W = (sel == 0) ? Wq : (sel == 1) ? Wk : Wv;
        w = W[k * 768 + col];
    } else {
        w = Wp[k * 768 + (n - 2304)];
    }
    __half h = __float2half_rn(w);
    __half l = __float2half_rn(w - __half2float(h));
    g_wt_hi[(size_t)n * 768 + k] = h;
    g_wt_lo[(size_t)n * 768 + k] = l;
}

// ---------------------------------------------------------------------------
// x prep: round x fp32 -> fp16.
// ---------------------------------------------------------------------------
__global__ __launch_bounds__(256) void xprep_kernel(const float* __restrict__ x)
{
    size_t idx = ((size_t)blockIdx.x * 256 + threadIdx.x) * 4;
    if (idx >= (size_t)M_ROWS * DIM) return;
    float4 v = *(const float4*)(x + idx);
    __half2 a = __floats2half2_rn(v.x, v.y);
    __half2 b = __floats2half2_rn(v.z, v.w);
    *(uint2*)(g_x_h + idx) = make_uint2(*(uint32_t*)&a, *(uint32_t*)&b);
}

// ---------------------------------------------------------------------------
// HMMA fp16 2-pass GEMM, cp.async 3-stage.
// Tile 256x128, K-chunk 64, 512 threads = 16 warps (4m x 4n), warp tile 64x32.
// ---------------------------------------------------------------------------
#define A_TILE_B  (256 * 144)                     // 36864
#define B_TILE_B  (128 * 144)                     // 18432
#define STAGE_B   (A_TILE_B + 2 * B_TILE_B)       // 73728
#define GSM_TOTAL (3 * STAGE_B)                   // 221184

template <bool BIAS>
__global__ __launch_bounds__(512, 1) void hmma_gemm(
    const __half* __restrict__ A,
    const __half* __restrict__ Bhi, const __half* __restrict__ Blo,
    float* __restrict__ C, const float* __restrict__ bias, int ldc)
{
    extern __shared__ char smem[];
    const uint32_t sbase = smem_u32(smem);

    const int tid  = threadIdx.x;
    const int wid  = tid >> 5;
    const int lane = tid & 31;
    const int wm   = wid & 3;
    const int wn   = wid >> 2;
    const int g    = lane >> 2;
    const int tg   = lane & 3;
    const int brow = blockIdx.y * 256;
    const int bcol = blockIdx.x * 128;

    float acc[4][4][4];
    #pragma unroll
    for (int m = 0; m < 4; ++m)
        #pragma unroll
        for (int n = 0; n < 4; ++n)
            #pragma unroll
            for (int r = 0; r < 4; ++r) acc[m][n][r] = 0.f;

    auto load_stage = [&](int st, int chunk) {
        const int k0 = chunk * 64;
        const uint32_t sa = sbase + st * STAGE_B;
        #pragma unroll
        for (int it = 0; it < 4; ++it) {
            int idx = tid + it * 512;
            int row = idx >> 3, q = idx & 7;
            cp16(sa + (uint32_t)(row * 144 + q * 16),
                 A + (size_t)(brow + row) * 768 + k0 + q * 8);
        }
        #pragma unroll
        for (int it = 0; it < 4; ++it) {
            int idx = tid + it * 512;
            int tile = idx >> 10, row = (idx >> 3) & 127, q = idx & 7;
            const __half* src = (tile ? Blo : Bhi) + (size_t)(bcol + row) * 768 + k0 + q * 8;
            cp16(sa + A_TILE_B + tile * B_TILE_B + (uint32_t)(row * 144 + q * 16), src);
        }
        asm volatile("cp.async.commit_group;");
    };

    load_stage(0, 0);
    load_stage(1, 1);

    for (int c = 0; c < 12; ++c) {
        if (c <= 9) {
            load_stage((c + 2) % 3, c + 2);
            asm volatile("cp.async.wait_group 2;");
        } else if (c == 10) {
            asm volatile("cp.async.wait_group 1;");
        } else {
            asm volatile("cp.async.wait_group 0;");
        }
        __syncthreads();

        const char* sa  = smem + (c % 3) * STAGE_B;
        const char* aP  = sa;
        const char* bHi = sa + A_TILE_B;
        const char* bLo = sa + A_TILE_B + B_TILE_B;

        #pragma unroll
        for (int s = 0; s < 4; ++s) {
            const int kb = s * 16 + tg * 2;
            uint32_t bh[4][2], bl[4][2];
            #pragma unroll
            for (int n = 0; n < 4; ++n) {
                uint32_t ro = (uint32_t)((wn * 32 + n * 8 + g) * 144 + kb * 2);
                bh[n][0] = *(const uint32_t*)(bHi + ro);
                bh[n][1] = *(const uint32_t*)(bHi + ro + 16);
                bl[n][0] = *(const uint32_t*)(bLo + ro);
                bl[n][1] = *(const uint32_t*)(bLo + ro + 16);
            }
            #pragma unroll
            for (int m = 0; m < 4; ++m) {
                uint32_t ro = (uint32_t)((wm * 64 + m * 16 + g) * 144 + kb * 2);
                uint32_t a[4];
                a[0] = *(const uint32_t*)(aP + ro);
                a[1] = *(const uint32_t*)(aP + ro + 8 * 144);
                a[2] = *(const uint32_t*)(aP + ro + 16);
                a[3] = *(const uint32_t*)(aP + ro + 8 * 144 + 16);
                #pragma unroll
                for (int n = 0; n < 4; ++n) {
                    mma_f16(acc[m][n], a, bh[n]);
                    mma_f16(acc[m][n], a, bl[n]);
                }
            }
        }
        __syncthreads();
    }

    #pragma unroll
    for (int n = 0; n < 4; ++n) {
        int col = bcol + wn * 32 + n * 8 + tg * 2;
        float b0 = 0.f, b1 = 0.f;
        if (BIAS) { b0 = bias[col]; b1 = bias[col + 1]; }
        #pragma unroll
        for (int m = 0; m < 4; ++m) {
            int row0 = brow + wm * 64 + m * 16 + g;
            *(float2*)(C + (size_t)row0 * ldc + col) =
                make_float2(acc[m][n][0] + b0, acc[m][n][1] + b1);
            *(float2*)(C + (size_t)(row0 + 8) * ldc + col) =
                make_float2(acc[m][n][2] + b0, acc[m][n][3] + b1);
        }
    }
}

// ---------------------------------------------------------------------------
// Grouped attention: 1 head/CTA, 128 threads, register-blocked, 30.6 KB smem
// (static) -> 7 CTAs/SM. QK: 2q x 4k per thread. PV: 2q x 8d per thread.
// ---------------------------------------------------------------------------
#define PSS 34

__global__ __launch_bounds__(128) void attn_kernel(
    const float* __restrict__ qkv, float* __restrict__ out)
{
    const int g  = blockIdx.x;   // 0..48
    const int h  = blockIdx.y;   // 0..11
    const int bs = blockIdx.z;   // 0..31
    const int s1 = g / 7, s2 = g % 7;
    const int tid = threadIdx.x;

    __shared__ float qs[32 * 68];
    __shared__ float ks[32 * 68];
    __shared__ float vs[32 * 68];
    __shared__ float ps[32 * PSS];
    __shared__ int   rowbase[32];

    if (tid < 32) {
        int j = tid;
        int view = j & 7, t2 = (j >> 3) & 1, t1 = j >> 4;
        rowbase[j] = (bs * 8 + view) * 196 + (t1 * 7 + s1) * 14 + (t2 * 7 + s2);
    }
    __syncthreads();

    // load q/k/v: 3 x 512 float4, 128 threads x 12 iters
    #pragma unroll
    for (int it = 0; it < 12; ++it) {
        int idx = tid + it * 128;         // 0..1535
        int arr = idx >> 9;               // 0..2
        int r = (idx >> 4) & 31, d4 = idx & 15;
        size_t base = (size_t)rowbase[r] * QKV_LD + h * 64 + d4 * 4 + arr * 768;
        float* dst = (arr == 0) ? qs : (arr == 1) ? ks : vs;
        *(float4*)(dst + r * 68 + d4 * 4) = *(const float4*)(qkv + base);
    }
    __syncthreads();

    // ---- QK: queries {iq, iq+16}, keys {js + 8kj} ----
    {
        const int iq = tid >> 3;          // 0..15
        const int js = tid & 7;           // 0..7
        float s[2][4];
        #pragma unroll
        for (int a = 0; a < 2; ++a)
            #pragma unroll
            for (int b = 0; b < 4; ++b) s[a][b] = 0.f;

        #pragma unroll
        for (int k4 = 0; k4 < 16; ++k4) {
            float4 qv[2], kv[4];
            qv[0] = *(const float4*)(qs + iq * 68 + k4 * 4);
            qv[1] = *(const float4*)(qs + (iq + 16) * 68 + k4 * 4);
            #pragma unroll
            for (int kj = 0; kj < 4; ++kj)
                kv[kj] = *(const float4*)(ks + (js + 8 * kj) * 68 + k4 * 4);
            #pragma unroll
            for (int a = 0; a < 2; ++a)
                #pragma unroll
                for (int kj = 0; kj < 4; ++kj)
                    s[a][kj] += qv[a].x * kv[kj].x + qv[a].y * kv[kj].y
                              + qv[a].z * kv[kj].z + qv[a].w * kv[kj].w;
        }
        #pragma unroll
        for (int a = 0; a < 2; ++a) {
            float mm = s[a][0] * 0.125f;
            #pragma unroll
            for (int kj = 0; kj < 4; ++kj) { s[a][kj] *= 0.125f; mm = fmaxf(mm, s[a][kj]); }
            mm = fmaxf(mm, __shfl_xor_sync(0xffffffffu, mm, 1));
            mm = fmaxf(mm, __shfl_xor_sync(0xffffffffu, mm, 2));
            mm = fmaxf(mm, __shfl_xor_sync(0xffffffffu, mm, 4));
            float sum = 0.f;
            #pragma unroll
            for (int kj = 0; kj < 4; ++kj) { s[a][kj] = expf(s[a][kj] - mm); sum += s[a][kj]; }
            sum += __shfl_xor_sync(0xffffffffu, sum, 1);
            sum += __shfl_xor_sync(0xffffffffu, sum, 2);
            sum += __shfl_xor_sync(0xffffffffu, sum, 4);
            float inv = 1.f / sum;
            #pragma unroll
            for (int kj = 0; kj < 4; ++kj)
                ps[(iq + 16 * a) * PSS + js + 8 * kj] = s[a][kj] * inv;
        }
    }
    __syncthreads();

    // ---- PV: queries {qp, qp+16}, dims {ds*8 .. +7} ----
    {
        const int qp = tid >> 3;          // 0..15
        const int ds = tid & 7;           // 0..7
        float o[2][8];
        #pragma unroll
        for (int a = 0; a < 2; ++a)
            #pragma unroll
            for (int b = 0; b < 8; ++b) o[a][b] = 0.f;

        #pragma unroll 4
        for (int j = 0; j < 32; ++j) {
            float4 v0 = *(const float4*)(vs + j * 68 + ds * 8);
            float4 v1 = *(const float4*)(vs + j * 68 + ds * 8 + 4);
            float p0 = ps[qp * PSS + j];
            float p1 = ps[(qp + 16) * PSS + j];
            o[0][0] += p0 * v0.x; o[0][1] += p0 * v0.y;
            o[0][2] += p0 * v0.z; o[0][3] += p0 * v0.w;
            o[0][4] += p0 * v1.x; o[0][5] += p0 * v1.y;
            o[0][6] += p0 * v1.z; o[0][7] += p0 * v1.w;
            o[1][0] += p1 * v0.x; o[1][1] += p1 * v0.y;
            o[1][2] += p1 * v0.z; o[1][3] += p1 * v0.w;
            o[1][4] += p1 * v1.x; o[1][5] += p1 * v1.y;
            o[1][6] += p1 * v1.z; o[1][7] += p1 * v1.w;
        }
        #pragma unroll
        for (int a = 0; a < 2; ++a) {
            size_t ob = (size_t)rowbase[qp + 16 * a] * DIM + h * 64 + ds * 8;
            *(float4*)(out + ob)     = make_float4(o[a][0], o[a][1], o[a][2], o[a][3]);
            *(float4*)(out + ob + 4) = make_float4(o[a][4], o[a][5], o[a][6], o[a][7]);
        }
    }
}

// ---------------------------------------------------------------------------
// Depthwise 3x3 conv (padded halo) + att add -> fp16 A for proj GEMM.
// ---------------------------------------------------------------------------
__global__ __launch_bounds__(256) void conv_split_kernel(
    const float* __restrict__ qkv, const float* __restrict__ att,
    const float* __restrict__ cw, const float* __restrict__ cb,
    __half* __restrict__ ah)
{
    const int chunk = blockIdx.x;   // 0..23
    const int b     = blockIdx.y;   // 0..255
    const int ch0   = chunk * 32;
    const int tid   = threadIdx.x;

    __shared__ float sh[256 * 32];
    __shared__ float w9[32 * 9];
    __shared__ float bb[32];

    #pragma unroll
    for (int i = tid; i < 2048; i += 256)
        ((float4*)sh)[i] = make_float4(0.f, 0.f, 0.f, 0.f);
    for (int i = tid; i < 32 * 9; i += 256)
        w9[i] = cw[ch0 * 9 + i];
    if (tid < 32) bb[tid] = cb[ch0 + tid];
    __syncthreads();

    for (int idx = tid; idx < 196 * 8; idx += 256) {
        int n = idx >> 3, q = idx & 7;
        int r = n / 14, c = n % 14;
        float4 v = *(const float4*)(qkv + (size_t)(b * 196 + n) * QKV_LD + 1536 + ch0 + q * 4);
        *(float4*)&sh[((r + 1) * 16 + (c + 1)) * 32 + q * 4] = v;
    }
    __syncthreads();

    for (int idx = tid; idx < 196 * 16; idx += 256) {
        int n = idx >> 4, cp = idx & 15;
        int r = n / 14, c = n % 14;
        int p0 = (r + 1) * 16 + (c + 1);
        int cc = cp * 2;
        float a0 = bb[cc], a1 = bb[cc + 1];
        #pragma unroll
        for (int dr = -1; dr <= 1; ++dr)
            #pragma unroll
            for (int dc = -1; dc <= 1; ++dc) {
                int tp = (dr + 1) * 3 + (dc + 1);
                const float* sp = &sh[(p0 + dr * 16 + dc) * 32 + cc];
                a0 += w9[cc * 9 + tp] * sp[0];
                a1 += w9[(cc + 1) * 9 + tp] * sp[1];
            }
        size_t o = (size_t)(b * 196 + n) * DIM + ch0 + cc;
        a0 += att[o];
        a1 += att[o + 1];
        __half2 hv = __floats2half2_rn(a0, a1);
        *(uint32_t*)(ah + o) = *(uint32_t*)&hv;
    }
}

// ---------------------------------------------------------------------------
extern "C" void kernel_launch(void* const* d_in, const int* in_sizes, int n_in,
                              void* d_out, int out_size)
{
    const float* x  = (const float*)d_in[0];
    const float* Wq = (const float*)d_in[2];
    const float* Wk = (const float*)d_in[3];
    const float* Wv = (const float*)d_in[4];
    const float* Wp = (const float*)d_in[5];
    const float* bp = (const float*)d_in[6];
    const float* cw = (const float*)d_in[7];
    const float* cb = (const float*)d_in[8];
    float* out = (float*)d_out;

    float *qkv_p = nullptr, *att_p = nullptr;
    __half *wth = nullptr, *wtl = nullptr, *xh = nullptr, *ath = nullptr;
    cudaGetSymbolAddress((void**)&qkv_p, g_qkv);
    cudaGetSymbolAddress((void**)&att_p, g_att);
    cudaGetSymbolAddress((void**)&wth, g_wt_hi);
    cudaGetSymbolAddress((void**)&wtl, g_wt_lo);
    cudaGetSymbolAddress((void**)&xh, g_x_h);
    cudaGetSymbolAddress((void**)&ath, g_att_h);

    cudaFuncSetAttribute(hmma_gemm<false>, cudaFuncAttributeMaxDynamicSharedMemorySize, GSM_TOTAL);
    cudaFuncSetAttribute(hmma_gemm<true>,  cudaFuncAttributeMaxDynamicSharedMemorySize, GSM_TOTAL);

    // Prep: weight split+transpose, x round
    wprep_kernel<<<(3072 * 768 + 255) / 256, 256>>>(Wq, Wk, Wv, Wp);
    xprep_kernel<<<(M_ROWS * DIM / 4 + 255) / 256, 256>>>(x);

    // QKV projections (fused N=2304) -> g_qkv fp32
    hmma_gemm<false><<<dim3(18, 196), 512, GSM_TOTAL>>>(
        xh, wth, wtl, qkv_p, nullptr, QKV_LD);

    // Grouped attention -> g_att (fp32), 1 head per CTA
    attn_kernel<<<dim3(49, 12, 32), 128>>>(qkv_p, att_p);

    // Conv + add -> fp16 A
    conv_split_kernel<<<dim3(24, 256), 256>>>(qkv_p, att_p, cw, cb, ath);

    // Output projection + bias -> d_out
    hmma_gemm<true><<<dim3(6, 196), 512, GSM_TOTAL>>>(
        ath, wth + (size_t)2304 * 768, wtl + (size_t)2304 * 768, out, bp, DIM);
}

// round 15
// speedup vs baseline: 3.4753x; 1.0648x over previous
#include <cuda_runtime.h>
#include <cuda_fp16.h>
#include <cstdint>

// ---------------------------------------------------------------------------
// LGA attention. fp16 2-pass HMMA GEMMs; fp16 qkv end-to-end.
// M = 50176, K = 768, N(QKV fused) = 2304, N(proj) = 768.
// ---------------------------------------------------------------------------

#define M_ROWS 50176
#define DIM 768
#define QKV_LD 2304

__device__ __half g_qkv_h[(size_t)M_ROWS * QKV_LD];
__device__ float g_att[(size_t)M_ROWS * DIM];
__device__ __half g_x_h[(size_t)M_ROWS * DIM];
__device__ __half g_att_h[(size_t)M_ROWS * DIM];
// fp16 transposed weights: rows 0..2303 = [Wq|Wk|Wv] cols, 2304..3071 = Wp cols.
__device__ __half g_wt_hi[(size_t)3072 * DIM];
__device__ __half g_wt_lo[(size_t)3072 * DIM];

__device__ __forceinline__ void mma_f16(float* d, const uint32_t* a, const uint32_t* b) {
    asm volatile(
        "mma.sync.aligned.m16n8k16.row.col.f32.f16.f16.f32 "
        "{%0,%1,%2,%3}, {%4,%5,%6,%7}, {%8,%9}, {%0,%1,%2,%3};\n"
        : "+f"(d[0]), "+f"(d[1]), "+f"(d[2]), "+f"(d[3])
        : "r"(a[0]), "r"(a[1]), "r"(a[2]), "r"(a[3]), "r"(b[0]), "r"(b[1]));
}

__device__ __forceinline__ uint32_t smem_u32(const void* p) {
    uint32_t a;
    asm("{ .reg .u64 t; cvta.to.shared.u64 t, %1; cvt.u32.u64 %0, t; }" : "=r"(a) : "l"(p));
    return a;
}
__device__ __forceinline__ void cp16(uint32_t dst, const void* src) {
    asm volatile("cp.async.cg.shared.global [%0], [%1], 16;" :: "r"(dst), "l"(src));
}
__device__ __forceinline__ float2 h2f(uint32_t w) {
    __half2 h = *(__half2*)&w;
    return __half22float2(h);
}

// ---------------------------------------------------------------------------
// Weight prep: split + transpose into g_wt_hi/lo (rows = output cols).
// ---------------------------------------------------------------------------
__global__ __launch_bounds__(256) void wprep_kernel(
    const float* __restrict__ Wq, const float* __restrict__ Wk,
    const float* __restrict__ Wv, const float* __restrict__ Wp)
{
    int idx = blockIdx.x * 256 + threadIdx.x;
    if (idx >= 3072 * 768) return;
    int n = idx / 768, k = idx % 768;
    float w;
    if (n < 2304) {
        int sel = n / 768, col = n % 768;
        const float* W = (sel == 0) ? Wq : (sel == 1) ? Wk : Wv;
        w = W[k * 768 + col];
    } else {
        w = Wp[k * 768 + (n - 2304)];
    }
    __half h = __float2half_rn(w);
    __half l = __float2half_rn(w - __half2float(h));
    g_wt_hi[(size_t)n * 768 + k] = h;
    g_wt_lo[(size_t)n * 768 + k] = l;
}

// ---------------------------------------------------------------------------
// x prep: round x fp32 -> fp16.
// ---------------------------------------------------------------------------
__global__ __launch_bounds__(256) void xprep_kernel(const float* __restrict__ x)
{
    size_t idx = ((size_t)blockIdx.x * 256 + threadIdx.x) * 4;
    if (idx >= (size_t)M_ROWS * DIM) return;
    float4 v = *(const float4*)(x + idx);
    __half2 a = __floats2half2_rn(v.x, v.y);
    __half2 b = __floats2half2_rn(v.z, v.w);
    *(uint2*)(g_x_h + idx) = make_uint2(*(uint32_t*)&a, *(uint32_t*)&b);
}

// ---------------------------------------------------------------------------
// HMMA fp16 2-pass GEMM, cp.async 3-stage.
// Tile 256x128, K-chunk 64, 512 threads = 16 warps (4m x 4n), warp tile 64x32.
// HOUT: write fp16 output (qkv), else fp32 (+bias).
// ---------------------------------------------------------------------------
#define A_TILE_B  (256 * 144)
#define B_TILE_B  (128 * 144)
#define STAGE_B   (A_TILE_B + 2 * B_TILE_B)       // 73728
#define GSM_TOTAL (3 * STAGE_B)                   // 221184

template <bool BIAS, bool HOUT>
__global__ __launch_bounds__(512, 1) void hmma_gemm(
    const __half* __restrict__ A,
    const __half* __restrict__ Bhi, const __half* __restrict__ Blo,
    void* __restrict__ Cv, const float* __restrict__ bias, int ldc)
{
    extern __shared__ char smem[];
    const uint32_t sbase = smem_u32(smem);

    const int tid  = threadIdx.x;
    const int wid  = tid >> 5;
    const int lane = tid & 31;
    const int wm   = wid & 3;
    const int wn   = wid >> 2;
    const int g    = lane >> 2;
    const int tg   = lane & 3;
    const int brow = blockIdx.y * 256;
    const int bcol = blockIdx.x * 128;

    float acc[4][4][4];
    #pragma unroll
    for (int m = 0; m < 4; ++m)
        #pragma unroll
        for (int n = 0; n < 4; ++n)
            #pragma unroll
            for (int r = 0; r < 4; ++r) acc[m][n][r] = 0.f;

    auto load_stage = [&](int st, int chunk) {
        const int k0 = chunk * 64;
        const uint32_t sa = sbase + st * STAGE_B;
        #pragma unroll
        for (int it = 0; it < 4; ++it) {
            int idx = tid + it * 512;
            int row = idx >> 3, q = idx & 7;
            cp16(sa + (uint32_t)(row * 144 + q * 16),
                 A + (size_t)(brow + row) * 768 + k0 + q * 8);
        }
        #pragma unroll
        for (int it = 0; it < 4; ++it) {
            int idx = tid + it * 512;
            int tile = idx >> 10, row = (idx >> 3) & 127, q = idx & 7;
            const __half* src = (tile ? Blo : Bhi) + (size_t)(bcol + row) * 768 + k0 + q * 8;
            cp16(sa + A_TILE_B + tile * B_TILE_B + (uint32_t)(row * 144 + q * 16), src);
        }
        asm volatile("cp.async.commit_group;");
    };

    load_stage(0, 0);
    load_stage(1, 1);

    for (int c = 0; c < 12; ++c) {
        if (c <= 9) {
            load_stage((c + 2) % 3, c + 2);
            asm volatile("cp.async.wait_group 2;");
        } else if (c == 10) {
            asm volatile("cp.async.wait_group 1;");
        } else {
            asm volatile("cp.async.wait_group 0;");
        }
        __syncthreads();

        const char* sa  = smem + (c % 3) * STAGE_B;
        const char* aP  = sa;
        const char* bHi = sa + A_TILE_B;
        const char* bLo = sa + A_TILE_B + B_TILE_B;

        #pragma unroll
        for (int s = 0; s < 4; ++s) {
            const int kb = s * 16 + tg * 2;
            uint32_t bh[4][2], bl[4][2];
            #pragma unroll
            for (int n = 0; n < 4; ++n) {
                uint32_t ro = (uint32_t)((wn * 32 + n * 8 + g) * 144 + kb * 2);
                bh[n][0] = *(const uint32_t*)(bHi + ro);
                bh[n][1] = *(const uint32_t*)(bHi + ro + 16);
                bl[n][0] = *(const uint32_t*)(bLo + ro);
                bl[n][1] = *(const uint32_t*)(bLo + ro + 16);
            }
            #pragma unroll
            for (int m = 0; m < 4; ++m) {
                uint32_t ro = (uint32_t)((wm * 64 + m * 16 + g) * 144 + kb * 2);
                uint32_t a[4];
                a[0] = *(const uint32_t*)(aP + ro);
                a[1] = *(const uint32_t*)(aP + ro + 8 * 144);
                a[2] = *(const uint32_t*)(aP + ro + 16);
                a[3] = *(const uint32_t*)(aP + ro + 8 * 144 + 16);
                #pragma unroll
                for (int n = 0; n < 4; ++n) {
                    mma_f16(acc[m][n], a, bh[n]);
                    mma_f16(acc[m][n], a, bl[n]);
                }
            }
        }
        __syncthreads();
    }

    #pragma unroll
    for (int n = 0; n < 4; ++n) {
        int col = bcol + wn * 32 + n * 8 + tg * 2;
        float b0 = 0.f, b1 = 0.f;
        if (BIAS) { b0 = bias[col]; b1 = bias[col + 1]; }
        #pragma unroll
        for (int m = 0; m < 4; ++m) {
            int row0 = brow + wm * 64 + m * 16 + g;
            if (HOUT) {
                __half* C = (__half*)Cv;
                __half2 h0 = __floats2half2_rn(acc[m][n][0] + b0, acc[m][n][1] + b1);
                __half2 h1 = __floats2half2_rn(acc[m][n][2] + b0, acc[m][n][3] + b1);
                *(uint32_t*)(C + (size_t)row0 * ldc + col)       = *(uint32_t*)&h0;
                *(uint32_t*)(C + (size_t)(row0 + 8) * ldc + col) = *(uint32_t*)&h1;
            } else {
                float* C = (float*)Cv;
                *(float2*)(C + (size_t)row0 * ldc + col) =
                    make_float2(acc[m][n][0] + b0, acc[m][n][1] + b1);
                *(float2*)(C + (size_t)(row0 + 8) * ldc + col) =
                    make_float2(acc[m][n][2] + b0, acc[m][n][3] + b1);
            }
        }
    }
}

// ---------------------------------------------------------------------------
// Grouped attention: 1 head/CTA, 128 threads, fp16 smem (144B rows), fp32 math.
// QK: 2q x 4k per thread, 8 k8-iters. PV: 2q x 8d per thread, 1 LDS.128 per j.
// ---------------------------------------------------------------------------
#define PSS 34

__global__ __launch_bounds__(128) void attn_kernel(
    const __half* __restrict__ qkv, float* __restrict__ out)
{
    const int g  = blockIdx.x;   // 0..48
    const int h  = blockIdx.y;   // 0..11
    const int bs = blockIdx.z;   // 0..31
    const int s1 = g / 7, s2 = g % 7;
    const int tid = threadIdx.x;

    __shared__ uint32_t qs[32 * 36];   // 36 words = 144B row (64 halves + pad)
    __shared__ uint32_t ks[32 * 36];
    __shared__ uint32_t vs[32 * 36];
    __shared__ float ps[32 * PSS];
    __shared__ int rowbase[32];

    if (tid < 32) {
        int j = tid;
        int view = j & 7, t2 = (j >> 3) & 1, t1 = j >> 4;
        rowbase[j] = (bs * 8 + view) * 196 + (t1 * 7 + s1) * 14 + (t2 * 7 + s2);
    }
    __syncthreads();

    // load q/k/v: 3 arrays x 32 rows x 8 chunks (16B) = 768 loads
    #pragma unroll
    for (int it = 0; it < 6; ++it) {
        int idx = tid + it * 128;         // 0..767
        int arr = idx >> 8;               // 0..2
        int r = (idx >> 3) & 31, c8 = idx & 7;
        const __half* src = qkv + (size_t)rowbase[r] * QKV_LD + h * 64 + arr * 768 + c8 * 8;
        uint4 v = *(const uint4*)src;
        uint32_t* dst = (arr == 0) ? qs : (arr == 1) ? ks : vs;
        *(uint4*)(dst + r * 36 + c8 * 4) = v;
    }
    __syncthreads();

    const uint4* qs4 = (const uint4*)qs;
    const uint4* ks4 = (const uint4*)ks;
    const uint4* vs4 = (const uint4*)vs;

    // ---- QK: queries {iq, iq+16}, keys {js + 8kj} ----
    {
        const int iq = tid >> 3;          // 0..15
        const int js = tid & 7;           // 0..7
        float s[2][4];
        #pragma unroll
        for (int a = 0; a < 2; ++a)
            #pragma unroll
            for (int b = 0; b < 4; ++b) s[a][b] = 0.f;

        #pragma unroll
        for (int k8 = 0; k8 < 8; ++k8) {
            float qf[2][8];
            #pragma unroll
            for (int a = 0; a < 2; ++a) {
                uint4 qw = qs4[(iq + 16 * a) * 9 + k8];
                float2 f0 = h2f(qw.x), f1 = h2f(qw.y), f2 = h2f(qw.z), f3 = h2f(qw.w);
                qf[a][0] = f0.x; qf[a][1] = f0.y; qf[a][2] = f1.x; qf[a][3] = f1.y;
                qf[a][4] = f2.x; qf[a][5] = f2.y; qf[a][6] = f3.x; qf[a][7] = f3.y;
            }
            #pragma unroll
            for (int kj = 0; kj < 4; ++kj) {
                uint4 kw = ks4[(js + 8 * kj) * 9 + k8];
                float2 f0 = h2f(kw.x), f1 = h2f(kw.y), f2 = h2f(kw.z), f3 = h2f(kw.w);
                float kf[8] = {f0.x, f0.y, f1.x, f1.y, f2.x, f2.y, f3.x, f3.y};
                #pragma unroll
                for (int a = 0; a < 2; ++a) {
                    float acc = 0.f;
                    #pragma unroll
                    for (int d = 0; d < 8; ++d) acc += qf[a][d] * kf[d];
                    s[a][kj] += acc;
                }
            }
        }
        #pragma unroll
        for (int a = 0; a < 2; ++a) {
            float mm = s[a][0] * 0.125f;
            #pragma unroll
            for (int kj = 0; kj < 4; ++kj) { s[a][kj] *= 0.125f; mm = fmaxf(mm, s[a][kj]); }
            mm = fmaxf(mm, __shfl_xor_sync(0xffffffffu, mm, 1));
            mm = fmaxf(mm, __shfl_xor_sync(0xffffffffu, mm, 2));
            mm = fmaxf(mm, __shfl_xor_sync(0xffffffffu, mm, 4));
            float sum = 0.f;
            #pragma unroll
            for (int kj = 0; kj < 4; ++kj) { s[a][kj] = expf(s[a][kj] - mm); sum += s[a][kj]; }
            sum += __shfl_xor_sync(0xffffffffu, sum, 1);
            sum += __shfl_xor_sync(0xffffffffu, sum, 2);
            sum += __shfl_xor_sync(0xffffffffu, sum, 4);
            float inv = 1.f / sum;
            #pragma unroll
            for (int kj = 0; kj < 4; ++kj)
                ps[(iq + 16 * a) * PSS + js + 8 * kj] = s[a][kj] * inv;
        }
    }
    __syncthreads();

    // ---- PV: queries {qp, qp+16}, dims {ds*8 .. +7} ----
    {
        const int qp = tid >> 3;          // 0..15
        const int ds = tid & 7;           // 0..7
        float o[2][8];
        #pragma unroll
        for (int a = 0; a < 2; ++a)
            #pragma unroll
            for (int b = 0; b < 8; ++b) o[a][b] = 0.f;

        #pragma unroll 4
        for (int j = 0; j < 32; ++j) {
            uint4 vw = vs4[j * 9 + ds];
            float2 v0 = h2f(vw.x), v1 = h2f(vw.y), v2 = h2f(vw.z), v3 = h2f(vw.w);
            float p0 = ps[qp * PSS + j];
            float p1 = ps[(qp + 16) * PSS + j];
            o[0][0] += p0 * v0.x; o[0][1] += p0 * v0.y;
            o[0][2] += p0 * v1.x; o[0][3] += p0 * v1.y;
            o[0][4] += p0 * v2.x; o[0][5] += p0 * v2.y;
            o[0][6] += p0 * v3.x; o[0][7] += p0 * v3.y;
            o[1][0] += p1 * v0.x; o[1][1] += p1 * v0.y;
            o[1][2] += p1 * v1.x; o[1][3] += p1 * v1.y;
            o[1][4] += p1 * v2.x; o[1][5] += p1 * v2.y;
            o[1][6] += p1 * v3.x; o[1][7] += p1 * v3.y;
        }
        #pragma unroll
        for (int a = 0; a < 2; ++a) {
            size_t ob = (size_t)rowbase[qp + 16 * a] * DIM + h * 64 + ds * 8;
            *(float4*)(out + ob)     = make_float4(o[a][0], o[a][1], o[a][2], o[a][3]);
            *(float4*)(out + ob + 4) = make_float4(o[a][4], o[a][5], o[a][6], o[a][7]);
        }
    }
}

// ---------------------------------------------------------------------------
// Depthwise 3x3 conv (padded halo) + att add -> fp16 A for proj GEMM.
// v read from fp16 qkv, converted into fp32 smem tile.
// ---------------------------------------------------------------------------
__global__ __launch_bounds__(256) void conv_split_kernel(
    const __half* __restrict__ qkv, const float* __restrict__ att,
    const float* __restrict__ cw, const float* __restrict__ cb,
    __half* __restrict__ ah)
{
    const int chunk = blockIdx.x;   // 0..23
    const int b     = blockIdx.y;   // 0..255
    const int ch0   = chunk * 32;
    const int tid   = threadIdx.x;

    __shared__ float sh[256 * 32];
    __shared__ float w9[32 * 9];
    __shared__ float bb[32];

    #pragma unroll
    for (int i = tid; i < 2048; i += 256)
        ((float4*)sh)[i] = make_float4(0.f, 0.f, 0.f, 0.f);
    for (int i = tid; i < 32 * 9; i += 256)
        w9[i] = cw[ch0 * 9 + i];
    if (tid < 32) bb[tid] = cb[ch0 + tid];
    __syncthreads();

    // 196 tokens x 4 chunks of 8 halves
    for (int idx = tid; idx < 196 * 4; idx += 256) {
        int n = idx >> 2, q = idx & 3;
        int r = n / 14, c = n % 14;
        uint4 w = *(const uint4*)(qkv + (size_t)(b * 196 + n) * QKV_LD + 1536 + ch0 + q * 8);
        float2 f0 = h2f(w.x), f1 = h2f(w.y), f2 = h2f(w.z), f3 = h2f(w.w);
        float* d = &sh[((r + 1) * 16 + (c + 1)) * 32 + q * 8];
        d[0] = f0.x; d[1] = f0.y; d[2] = f1.x; d[3] = f1.y;
        d[4] = f2.x; d[5] = f2.y; d[6] = f3.x; d[7] = f3.y;
    }
    __syncthreads();

    for (int idx = tid; idx < 196 * 16; idx += 256) {
        int n = idx >> 4, cp = idx & 15;
        int r = n / 14, c = n % 14;
        int p0 = (r + 1) * 16 + (c + 1);
        int cc = cp * 2;
        float a0 = bb[cc], a1 = bb[cc + 1];
        #pragma unroll
        for (int dr = -1; dr <= 1; ++dr)
            #pragma unroll
            for (int dc = -1; dc <= 1; ++dc) {
                int tp = (dr + 1) * 3 + (dc + 1);
                const float* sp = &sh[(p0 + dr * 16 + dc) * 32 + cc];
                a0 += w9[cc * 9 + tp] * sp[0];
                a1 += w9[(cc + 1) * 9 + tp] * sp[1];
            }
        size_t o = (size_t)(b * 196 + n) * DIM + ch0 + cc;
        a0 += att[o];
        a1 += att[o + 1];
        __half2 hv = __floats2half2_rn(a0, a1);
        *(uint32_t*)(ah + o) = *(uint32_t*)&hv;
    }
}

// ---------------------------------------------------------------------------
extern "C" void kernel_launch(void* const* d_in, const int* in_sizes, int n_in,
                              void* d_out, int out_size)
{
    const float* x  = (const float*)d_in[0];
    const float* Wq = (const float*)d_in[2];
    const float* Wk = (const float*)d_in[3];
    const float* Wv = (const float*)d_in[4];
    const float* Wp = (const float*)d_in[5];
    const float* bp = (const float*)d_in[6];
    const float* cw = (const float*)d_in[7];
    const float* cb = (const float*)d_in[8];
    float* out = (float*)d_out;

    float* att_p = nullptr;
    __half *qkv_p = nullptr, *wth = nullptr, *wtl = nullptr, *xh = nullptr, *ath = nullptr;
    cudaGetSymbolAddress((void**)&qkv_p, g_qkv_h);
    cudaGetSymbolAddress((void**)&att_p, g_att);
    cudaGetSymbolAddress((void**)&wth, g_wt_hi);
    cudaGetSymbolAddress((void**)&wtl, g_wt_lo);
    cudaGetSymbolAddress((void**)&xh, g_x_h);
    cudaGetSymbolAddress((void**)&ath, g_att_h);

    cudaFuncSetAttribute(hmma_gemm<false, true>, cudaFuncAttributeMaxDynamicSharedMemorySize, GSM_TOTAL);
    cudaFuncSetAttribute(hmma_gemm<true, false>, cudaFuncAttributeMaxDynamicSharedMemorySize, GSM_TOTAL);

    // Prep: weight split+transpose, x round
    wprep_kernel<<<(3072 * 768 + 255) / 256, 256>>>(Wq, Wk, Wv, Wp);
    xprep_kernel<<<(M_ROWS * DIM / 4 + 255) / 256, 256>>>(x);

    // QKV projections (fused N=2304) -> g_qkv_h fp16
    hmma_gemm<false, true><<<dim3(18, 196), 512, GSM_TOTAL>>>(
        xh, wth, wtl, qkv_p, nullptr, QKV_LD);

    // Grouped attention -> g_att (fp32), 1 head per CTA
    attn_kernel<<<dim3(49, 12, 32), 128>>>(qkv_p, att_p);

    // Conv + add -> fp16 A
    conv_split_kernel<<<dim3(24, 256), 256>>>(qkv_p, att_p, cw, cb, ath);

    // Output projection + bias -> d_out fp32
    hmma_gemm<true, false><<<dim3(6, 196), 512, GSM_TOTAL>>>(
        ath, wth + (size_t)2304 * 768, wtl + (size_t)2304 * 768, out, bp, DIM);
}

// round 17
// speedup vs baseline: 4.3515x; 1.2521x over previous
#include <cuda_runtime.h>
#include <cuda_fp16.h>
#include <cstdint>

// ---------------------------------------------------------------------------
// LGA attention. HMMA fp16 GEMMs: QKV single-pass (W-hi), proj 2-pass (hi+lo).
// M = 50176, K = 768, N(QKV fused) = 2304, N(proj) = 768.
// ---------------------------------------------------------------------------

#define M_ROWS 50176
#define DIM 768
#define QKV_LD 2304

__device__ __half g_qkv_h[(size_t)M_ROWS * QKV_LD];
__device__ float g_att[(size_t)M_ROWS * DIM];
__device__ __half g_x_h[(size_t)M_ROWS * DIM];
__device__ __half g_att_h[(size_t)M_ROWS * DIM];
// fp16 transposed weights: rows 0..2303 = [Wq|Wk|Wv] cols, 2304..3071 = Wp cols.
__device__ __half g_wt_hi[(size_t)3072 * DIM];
__device__ __half g_wt_lo[(size_t)3072 * DIM];

__device__ __forceinline__ void mma_f16(float* d, const uint32_t* a, const uint32_t* b) {
    asm volatile(
        "mma.sync.aligned.m16n8k16.row.col.f32.f16.f16.f32 "
        "{%0,%1,%2,%3}, {%4,%5,%6,%7}, {%8,%9}, {%0,%1,%2,%3};\n"
        : "+f"(d[0]), "+f"(d[1]), "+f"(d[2]), "+f"(d[3])
        : "r"(a[0]), "r"(a[1]), "r"(a[2]), "r"(a[3]), "r"(b[0]), "r"(b[1]));
}

__device__ __forceinline__ uint32_t smem_u32(const void* p) {
    uint32_t a;
    asm("{ .reg .u64 t; cvta.to.shared.u64 t, %1; cvt.u32.u64 %0, t; }" : "=r"(a) : "l"(p));
    return a;
}
__device__ __forceinline__ void cp16(uint32_t dst, const void* src) {
    asm volatile("cp.async.cg.shared.global [%0], [%1], 16;" :: "r"(dst), "l"(src));
}
__device__ __forceinline__ float2 h2f(uint32_t w) {
    __half2 h = *(__half2*)&w;
    return __half22float2(h);
}

// ---------------------------------------------------------------------------
// Weight prep: split + transpose into g_wt_hi/lo (rows = output cols).
// ---------------------------------------------------------------------------
__global__ __launch_bounds__(256) void wprep_kernel(
    const float* __restrict__ Wq, const float* __restrict__ Wk,
    const float* __restrict__ Wv, const float* __restrict__ Wp)
{
    int idx = blockIdx.x * 256 + threadIdx.x;
    if (idx >= 3072 * 768) return;
    int n = idx / 768, k = idx % 768;
    float w;
    if (n < 2304) {
        int sel = n / 768, col = n % 768;
        const float* W = (sel == 0) ? Wq : (sel == 1) ? Wk : Wv;
        w = W[k * 768 + col];
    } else {
        w = Wp[k * 768 + (n - 2304)];
    }
    __half h = __float2half_rn(w);
    __half l = __float2half_rn(w - __half2float(h));
    g_wt_hi[(size_t)n * 768 + k] = h;
    g_wt_lo[(size_t)n * 768 + k] = l;
}

// ---------------------------------------------------------------------------
// x prep: round x fp32 -> fp16.
// ---------------------------------------------------------------------------
__global__ __launch_bounds__(256) void xprep_kernel(const float* __restrict__ x)
{
    size_t idx = ((size_t)blockIdx.x * 256 + threadIdx.x) * 4;
    if (idx >= (size_t)M_ROWS * DIM) return;
    float4 v = *(const float4*)(x + idx);
    __half2 a = __floats2half2_rn(v.x, v.y);
    __half2 b = __floats2half2_rn(v.z, v.w);
    *(uint2*)(g_x_h + idx) = make_uint2(*(uint32_t*)&a, *(uint32_t*)&b);
}

// ---------------------------------------------------------------------------
// HMMA fp16 GEMM, cp.async 3-stage. TWOPASS: B = hi+lo (2x MMA); else hi only.
// Tile 256x128, K-chunk 64, 512 threads = 16 warps (4m x 4n), warp tile 64x32.
// HOUT: write fp16 output, else fp32 (+bias).
// ---------------------------------------------------------------------------
#define A_TILE_B  (256 * 144)
#define B_TILE_B  (128 * 144)

template <bool BIAS, bool HOUT, bool TWOPASS>
__global__ __launch_bounds__(512, 1) void hmma_gemm(
    const __half* __restrict__ A,
    const __half* __restrict__ Bhi, const __half* __restrict__ Blo,
    void* __restrict__ Cv, const float* __restrict__ bias, int ldc)
{
    constexpr int STAGE_B = A_TILE_B + (TWOPASS ? 2 : 1) * B_TILE_B;
    extern __shared__ char smem[];
    const uint32_t sbase = smem_u32(smem);

    const int tid  = threadIdx.x;
    const int wid  = tid >> 5;
    const int lane = tid & 31;
    const int wm   = wid & 3;
    const int wn   = wid >> 2;
    const int g    = lane >> 2;
    const int tg   = lane & 3;
    const int brow = blockIdx.y * 256;
    const int bcol = blockIdx.x * 128;

    float acc[4][4][4];
    #pragma unroll
    for (int m = 0; m < 4; ++m)
        #pragma unroll
        for (int n = 0; n < 4; ++n)
            #pragma unroll
            for (int r = 0; r < 4; ++r) acc[m][n][r] = 0.f;

    auto load_stage = [&](int st, int chunk) {
        const int k0 = chunk * 64;
        const uint32_t sa = sbase + st * STAGE_B;
        #pragma unroll
        for (int it = 0; it < 4; ++it) {
            int idx = tid + it * 512;
            int row = idx >> 3, q = idx & 7;
            cp16(sa + (uint32_t)(row * 144 + q * 16),
                 A + (size_t)(brow + row) * 768 + k0 + q * 8);
        }
        if (TWOPASS) {
            #pragma unroll
            for (int it = 0; it < 4; ++it) {
                int idx = tid + it * 512;
                int tile = idx >> 10, row = (idx >> 3) & 127, q = idx & 7;
                const __half* src = (tile ? Blo : Bhi) + (size_t)(bcol + row) * 768 + k0 + q * 8;
                cp16(sa + A_TILE_B + tile * B_TILE_B + (uint32_t)(row * 144 + q * 16), src);
            }
        } else {
            #pragma unroll
            for (int it = 0; it < 2; ++it) {
                int idx = tid + it * 512;
                int row = idx >> 3, q = idx & 7;
                cp16(sa + A_TILE_B + (uint32_t)(row * 144 + q * 16),
                     Bhi + (size_t)(bcol + row) * 768 + k0 + q * 8);
            }
        }
        asm volatile("cp.async.commit_group;");
    };

    load_stage(0, 0);
    load_stage(1, 1);

    for (int c = 0; c < 12; ++c) {
        if (c <= 9) {
            load_stage((c + 2) % 3, c + 2);
            asm volatile("cp.async.wait_group 2;");
        } else if (c == 10) {
            asm volatile("cp.async.wait_group 1;");
        } else {
            asm volatile("cp.async.wait_group 0;");
        }
        __syncthreads();

        const char* sa  = smem + (c % 3) * STAGE_B;
        const char* aP  = sa;
        const char* bHi = sa + A_TILE_B;
        const char* bLo = sa + A_TILE_B + B_TILE_B;

        #pragma unroll
        for (int s = 0; s < 4; ++s) {
            const int kb = s * 16 + tg * 2;
            uint32_t bh[4][2], bl[4][2];
            #pragma unroll
            for (int n = 0; n < 4; ++n) {
                uint32_t ro = (uint32_t)((wn * 32 + n * 8 + g) * 144 + kb * 2);
                bh[n][0] = *(const uint32_t*)(bHi + ro);
                bh[n][1] = *(const uint32_t*)(bHi + ro + 16);
                if (TWOPASS) {
                    bl[n][0] = *(const uint32_t*)(bLo + ro);
                    bl[n][1] = *(const uint32_t*)(bLo + ro + 16);
                }
            }
            #pragma unroll
            for (int m = 0; m < 4; ++m) {
                uint32_t ro = (uint32_t)((wm * 64 + m * 16 + g) * 144 + kb * 2);
                uint32_t a[4];
                a[0] = *(const uint32_t*)(aP + ro);
                a[1] = *(const uint32_t*)(aP + ro + 8 * 144);
                a[2] = *(const uint32_t*)(aP + ro + 16);
                a[3] = *(const uint32_t*)(aP + ro + 8 * 144 + 16);
                #pragma unroll
                for (int n = 0; n < 4; ++n) {
                    mma_f16(acc[m][n], a, bh[n]);
                    if (TWOPASS) mma_f16(acc[m][n], a, bl[n]);
                }
            }
        }
        __syncthreads();
    }

    #pragma unroll
    for (int n = 0; n < 4; ++n) {
        int col = bcol + wn * 32 + n * 8 + tg * 2;
        float b0 = 0.f, b1 = 0.f;
        if (BIAS) { b0 = bias[col]; b1 = bias[col + 1]; }
        #pragma unroll
        for (int m = 0; m < 4; ++m) {
            int row0 = brow + wm * 64 + m * 16 + g;
            if (HOUT) {
                __half* C = (__half*)Cv;
                __half2 h0 = __floats2half2_rn(acc[m][n][0] + b0, acc[m][n][1] + b1);
                __half2 h1 = __floats2half2_rn(acc[m][n][2] + b0, acc[m][n][3] + b1);
                *(uint32_t*)(C + (size_t)row0 * ldc + col)       = *(uint32_t*)&h0;
                *(uint32_t*)(C + (size_t)(row0 + 8) * ldc + col) = *(uint32_t*)&h1;
            } else {
                float* C = (float*)Cv;
                *(float2*)(C + (size_t)row0 * ldc + col) =
                    make_float2(acc[m][n][0] + b0, acc[m][n][1] + b1);
                *(float2*)(C + (size_t)(row0 + 8) * ldc + col) =
                    make_float2(acc[m][n][2] + b0, acc[m][n][3] + b1);
            }
        }
    }
}

// ---------------------------------------------------------------------------
// Grouped attention: 1 head/CTA, 128 threads, fp16 smem (144B rows), fp32 math.
// ---------------------------------------------------------------------------
#define PSS 34

__global__ __launch_bounds__(128) void attn_kernel(
    const __half* __restrict__ qkv, float* __restrict__ out)
{
    const int g  = blockIdx.x;   // 0..48
    const int h  = blockIdx.y;   // 0..11
    const int bs = blockIdx.z;   // 0..31
    const int s1 = g / 7, s2 = g % 7;
    const int tid = threadIdx.x;

    __shared__ uint32_t qs[32 * 36];
    __shared__ uint32_t ks[32 * 36];
    __shared__ uint32_t vs[32 * 36];
    __shared__ float ps[32 * PSS];
    __shared__ int rowbase[32];

    if (tid < 32) {
        int j = tid;
        int view = j & 7, t2 = (j >> 3) & 1, t1 = j >> 4;
        rowbase[j] = (bs * 8 + view) * 196 + (t1 * 7 + s1) * 14 + (t2 * 7 + s2);
    }
    __syncthreads();

    #pragma unroll
    for (int it = 0; it < 6; ++it) {
        int idx = tid + it * 128;         // 0..767
        int arr = idx >> 8;               // 0..2
        int r = (idx >> 3) & 31, c8 = idx & 7;
        const __half* src = qkv + (size_t)rowbase[r] * QKV_LD + h * 64 + arr * 768 + c8 * 8;
        uint4 v = *(const uint4*)src;
        uint32_t* dst = (arr == 0) ? qs : (arr == 1) ? ks : vs;
        *(uint4*)(dst + r * 36 + c8 * 4) = v;
    }
    __syncthreads();

    const uint4* qs4 = (const uint4*)qs;
    const uint4* ks4 = (const uint4*)ks;
    const uint4* vs4 = (const uint4*)vs;

    // ---- QK: queries {iq, iq+16}, keys {js + 8kj} ----
    {
        const int iq = tid >> 3;
        const int js = tid & 7;
        float s[2][4];
        #pragma unroll
        for (int a = 0; a < 2; ++a)
            #pragma unroll
            for (int b = 0; b < 4; ++b) s[a][b] = 0.f;

        #pragma unroll
        for (int k8 = 0; k8 < 8; ++k8) {
            float qf[2][8];
            #pragma unroll
            for (int a = 0; a < 2; ++a) {
                uint4 qw = qs4[(iq + 16 * a) * 9 + k8];
                float2 f0 = h2f(qw.x), f1 = h2f(qw.y), f2 = h2f(qw.z), f3 = h2f(qw.w);
                qf[a][0] = f0.x; qf[a][1] = f0.y; qf[a][2] = f1.x; qf[a][3] = f1.y;
                qf[a][4] = f2.x; qf[a][5] = f2.y; qf[a][6] = f3.x; qf[a][7] = f3.y;
            }
            #pragma unroll
            for (int kj = 0; kj < 4; ++kj) {
                uint4 kw = ks4[(js + 8 * kj) * 9 + k8];
                float2 f0 = h2f(kw.x), f1 = h2f(kw.y), f2 = h2f(kw.z), f3 = h2f(kw.w);
                float kf[8] = {f0.x, f0.y, f1.x, f1.y, f2.x, f2.y, f3.x, f3.y};
                #pragma unroll
                for (int a = 0; a < 2; ++a) {
                    float acc = 0.f;
                    #pragma unroll
                    for (int d = 0; d < 8; ++d) acc += qf[a][d] * kf[d];
                    s[a][kj] += acc;
                }
            }
        }
        #pragma unroll
        for (int a = 0; a < 2; ++a) {
            float mm = s[a][0] * 0.125f;
            #pragma unroll
            for (int kj = 0; kj < 4; ++kj) { s[a][kj] *= 0.125f; mm = fmaxf(mm, s[a][kj]); }
            mm = fmaxf(mm, __shfl_xor_sync(0xffffffffu, mm, 1));
            mm = fmaxf(mm, __shfl_xor_sync(0xffffffffu, mm, 2));
            mm = fmaxf(mm, __shfl_xor_sync(0xffffffffu, mm, 4));
            float sum = 0.f;
            #pragma unroll
            for (int kj = 0; kj < 4; ++kj) { s[a][kj] = expf(s[a][kj] - mm); sum += s[a][kj]; }
            sum += __shfl_xor_sync(0xffffffffu, sum, 1);
            sum += __shfl_xor_sync(0xffffffffu, sum, 2);
            sum += __shfl_xor_sync(0xffffffffu, sum, 4);
            float inv = 1.f / sum;
            #pragma unroll
            for (int kj = 0; kj < 4; ++kj)
                ps[(iq + 16 * a) * PSS + js + 8 * kj] = s[a][kj] * inv;
        }
    }
    __syncthreads();

    // ---- PV: queries {qp, qp+16}, dims {ds*8 .. +7} ----
    {
        const int qp = tid >> 3;
        const int ds = tid & 7;
        float o[2][8];
        #pragma unroll
        for (int a = 0; a < 2; ++a)
            #pragma unroll
            for (int b = 0; b < 8; ++b) o[a][b] = 0.f;

        #pragma unroll 4
        for (int j = 0; j < 32; ++j) {
            uint4 vw = vs4[j * 9 + ds];
            float2 v0 = h2f(vw.x), v1 = h2f(vw.y), v2 = h2f(vw.z), v3 = h2f(vw.w);
            float p0 = ps[qp * PSS + j];
            float p1 = ps[(qp + 16) * PSS + j];
            o[0][0] += p0 * v0.x; o[0][1] += p0 * v0.y;
            o[0][2] += p0 * v1.x; o[0][3] += p0 * v1.y;
            o[0][4] += p0 * v2.x; o[0][5] += p0 * v2.y;
            o[0][6] += p0 * v3.x; o[0][7] += p0 * v3.y;
            o[1][0] += p1 * v0.x; o[1][1] += p1 * v0.y;
            o[1][2] += p1 * v1.x; o[1][3] += p1 * v1.y;
            o[1][4] += p1 * v2.x; o[1][5] += p1 * v2.y;
            o[1][6] += p1 * v3.x; o[1][7] += p1 * v3.y;
        }
        #pragma unroll
        for (int a = 0; a < 2; ++a) {
            size_t ob = (size_t)rowbase[qp + 16 * a] * DIM + h * 64 + ds * 8;
            *(float4*)(out + ob)     = make_float4(o[a][0], o[a][1], o[a][2], o[a][3]);
            *(float4*)(out + ob + 4) = make_float4(o[a][4], o[a][5], o[a][6], o[a][7]);
        }
    }
}

// ---------------------------------------------------------------------------
// Depthwise 3x3 conv (padded halo) + att add -> fp16 A for proj GEMM.
// ---------------------------------------------------------------------------
__global__ __launch_bounds__(256) void conv_split_kernel(
    const __half* __restrict__ qkv, const float* __restrict__ att,
    const float* __restrict__ cw, const float* __restrict__ cb,
    __half* __restrict__ ah)
{
    const int chunk = blockIdx.x;
    const int b     = blockIdx.y;
    const int ch0   = chunk * 32;
    const int tid   = threadIdx.x;

    __shared__ float sh[256 * 32];
    __shared__ float w9[32 * 9];
    __shared__ float bb[32];

    #pragma unroll
    for (int i = tid; i < 2048; i += 256)
        ((float4*)sh)[i] = make_float4(0.f, 0.f, 0.f, 0.f);
    for (int i = tid; i < 32 * 9; i += 256)
        w9[i] = cw[ch0 * 9 + i];
    if (tid < 32) bb[tid] = cb[ch0 + tid];
    __syncthreads();

    for (int idx = tid; idx < 196 * 4; idx += 256) {
        int n = idx >> 2, q = idx & 3;
        int r = n / 14, c = n % 14;
        uint4 w = *(const uint4*)(qkv + (size_t)(b * 196 + n) * QKV_LD + 1536 + ch0 + q * 8);
        float2 f0 = h2f(w.x), f1 = h2f(w.y), f2 = h2f(w.z), f3 = h2f(w.w);
        float* d = &sh[((r + 1) * 16 + (c + 1)) * 32 + q * 8];
        d[0] = f0.x; d[1] = f0.y; d[2] = f1.x; d[3] = f1.y;
        d[4] = f2.x; d[5] = f2.y; d[6] = f3.x; d[7] = f3.y;
    }
    __syncthreads();

    for (int idx = tid; idx < 196 * 16; idx += 256) {
        int n = idx >> 4, cp = idx & 15;
        int r = n / 14, c = n % 14;
        int p0 = (r + 1) * 16 + (c + 1);
        int cc = cp * 2;
        float a0 = bb[cc], a1 = bb[cc + 1];
        #pragma unroll
        for (int dr = -1; dr <= 1; ++dr)
            #pragma unroll
            for (int dc = -1; dc <= 1; ++dc) {
                int tp = (dr + 1) * 3 + (dc + 1);
                const float* sp = &sh[(p0 + dr * 16 + dc) * 32 + cc];
                a0 += w9[cc * 9 + tp] * sp[0];
                a1 += w9[(cc + 1) * 9 + tp] * sp[1];
            }
        size_t o = (size_t)(b * 196 + n) * DIM + ch0 + cc;
        a0 += att[o];
        a1 += att[o + 1];
        __half2 hv = __floats2half2_rn(a0, a1);
        *(uint32_t*)(ah + o) = *(uint32_t*)&hv;
    }
}

// ---------------------------------------------------------------------------
extern "C" void kernel_launch(void* const* d_in, const int* in_sizes, int n_in,
                              void* d_out, int out_size)
{
    const float* x  = (const float*)d_in[0];
    const float* Wq = (const float*)d_in[2];
    const float* Wk = (const float*)d_in[3];
    const float* Wv = (const float*)d_in[4];
    const float* Wp = (const float*)d_in[5];
    const float* bp = (const float*)d_in[6];
    const float* cw = (const float*)d_in[7];
    const float* cb = (const float*)d_in[8];
    float* out = (float*)d_out;

    float* att_p = nullptr;
    __half *qkv_p = nullptr, *wth = nullptr, *wtl = nullptr, *xh = nullptr, *ath = nullptr;
    cudaGetSymbolAddress((void**)&qkv_p, g_qkv_h);
    cudaGetSymbolAddress((void**)&att_p, g_att);
    cudaGetSymbolAddress((void**)&wth, g_wt_hi);
    cudaGetSymbolAddress((void**)&wtl, g_wt_lo);
    cudaGetSymbolAddress((void**)&xh, g_x_h);
    cudaGetSymbolAddress((void**)&ath, g_att_h);

    const int GSM_QKV  = 3 * (A_TILE_B + B_TILE_B);       // 165888
    const int GSM_PROJ = 3 * (A_TILE_B + 2 * B_TILE_B);   // 221184
    cudaFuncSetAttribute(hmma_gemm<false, true, false>,
                         cudaFuncAttributeMaxDynamicSharedMemorySize, GSM_QKV);
    cudaFuncSetAttribute(hmma_gemm<true, false, true>,
                         cudaFuncAttributeMaxDynamicSharedMemorySize, GSM_PROJ);

    // Prep: weight split+transpose, x round
    wprep_kernel<<<(3072 * 768 + 255) / 256, 256>>>(Wq, Wk, Wv, Wp);
    xprep_kernel<<<(M_ROWS * DIM / 4 + 255) / 256, 256>>>(x);

    // QKV projections (fused N=2304), single-pass fp16 -> g_qkv_h
    hmma_gemm<false, true, false><<<dim3(18, 196), 512, GSM_QKV>>>(
        xh, wth, nullptr, qkv_p, nullptr, QKV_LD);

    // Grouped attention -> g_att (fp32), 1 head per CTA
    attn_kernel<<<dim3(49, 12, 32), 128>>>(qkv_p, att_p);

    // Conv + add -> fp16 A
    conv_split_kernel<<<dim3(24, 256), 256>>>(qkv_p, att_p, cw, cb, ath);

    // Output projection + bias (2-pass) -> d_out fp32
    hmma_gemm<true, false, true><<<dim3(6, 196), 512, GSM_PROJ>>>(
        ath, wth + (size_t)2304 * 768, wtl + (size_t)2304 * 768, out, bp, DIM);
}